// round 2
// baseline (speedup 1.0000x reference)
#include <cuda_runtime.h>

#define BB 32
#define NWD 127

__device__ float g_i2s[BB * 64 * 64 * 256];  // [b][r][w][o] (includes b_i2s)
__device__ float g_hbuf[BB * 64 * 64 * 64];  // [b][r][w][j]
__device__ float g_h[2][BB * 64 * 64];
__device__ float g_c[2][BB * 64 * 64];

__device__ __forceinline__ float sig_(float x) { return 1.0f / (1.0f + __expf(-x)); }

__global__ void zero_kernel() {
    int i = blockIdx.x * blockDim.x + threadIdx.x;
    g_h[0][i] = 0.f;
    g_c[0][i] = 0.f;
}

// i2s: g_i2s[b][r][w][o] = b_i2s[o] + sum_c inputs[b][c][r][w] * w_i2s[o][c]
__global__ __launch_bounds__(256) void i2s_kernel(const float* __restrict__ inputs,
                                                  const float* __restrict__ w_i2s,
                                                  const float* __restrict__ b_i2s) {
    __shared__ float xs[64 * 64];  // [c][w]
    int b = blockIdx.x >> 6, r = blockIdx.x & 63;
    int tid = threadIdx.x;
    for (int i = tid; i < 4096; i += 256) {
        int c = i >> 6, w = i & 63;
        xs[i] = inputs[((((b << 6) | c) << 6 | r) << 6) | w];
    }
    __syncthreads();

    int o = tid & 127, wh = tid >> 7;
    float wa[64], wb[64];
    const float4* pa = (const float4*)(w_i2s + (o << 6));
    const float4* pb = (const float4*)(w_i2s + ((o + 128) << 6));
#pragma unroll
    for (int k4 = 0; k4 < 16; k4++) {
        float4 va = pa[k4], vb = pb[k4];
        wa[4*k4] = va.x; wa[4*k4+1] = va.y; wa[4*k4+2] = va.z; wa[4*k4+3] = va.w;
        wb[4*k4] = vb.x; wb[4*k4+1] = vb.y; wb[4*k4+2] = vb.z; wb[4*k4+3] = vb.w;
    }
    float ba = b_i2s[o], bb = b_i2s[o + 128];
    float* ob = g_i2s + ((((b << 6) | r) << 6) << 8);
    for (int w = (wh << 5); w < (wh << 5) + 32; w++) {
        float a0 = ba, a1 = bb;
#pragma unroll
        for (int k = 0; k < 64; k++) {
            float x = xs[(k << 6) | w];
            a0 += x * wa[k];
            a1 += x * wb[k];
        }
        ob[(w << 8) | o] = a0;
        ob[((w << 8) | o) + 128] = a1;
    }
}

// one diagonal step: 128 blocks = 32 batches x 4 rowgroups of 16 state rows
__global__ __launch_bounds__(256) void step_kernel(int t,
                                                   const float* __restrict__ w_s2s,
                                                   const float* __restrict__ b_s2s,
                                                   const float* __restrict__ w_c2c,
                                                   const float* __restrict__ b_c2c,
                                                   const float* __restrict__ b_i2s) {
    __shared__ float hsb[4 * 5 * 64];   // 4 gate bands x rows q-1..q+3
    __shared__ float csb[17 * 64];      // c rows r0-1..r0+15
    __shared__ float gsm[16 * 256];     // sigmoid gates: band m, local row i -> [m*4+i][o]

    int b = blockIdx.x >> 2, rg = blockIdx.x & 3;
    int r0 = rg << 4, q0 = rg << 2;
    int tid = threadIdx.x;

    const float* hsrc = g_h[t & 1] + b * 4096;
    const float* csrc = g_c[t & 1] + b * 4096;
    float* hdst = g_h[(t + 1) & 1] + b * 4096;
    float* cdst = g_c[(t + 1) & 1] + b * 4096;

    for (int i = tid; i < 1280; i += 256) {
        int m = i / 320, ii = (i >> 6) % 5, k = i & 63;
        int row = q0 + 16 * m - 1 + ii;
        hsb[i] = (row >= 0) ? hsrc[row * 64 + k] : 0.f;
    }
    for (int i = tid; i < 1088; i += 256) {
        int row = r0 - 1 + (i >> 6);
        csb[i] = (row >= 0) ? csrc[row * 64 + (i & 63)] : 0.f;
    }
    __syncthreads();

    // phase 1: 16 gate rows x 256 outputs
    {
        int o = tid;
        float w0[64], w1[64];
        const float4* wp = (const float4*)(w_s2s + o * 128);
#pragma unroll
        for (int k2 = 0; k2 < 32; k2++) {
            float4 v = wp[k2];
            w0[2*k2] = v.x; w1[2*k2] = v.y; w0[2*k2+1] = v.z; w1[2*k2+1] = v.w;
        }
        float bs = b_s2s[o], bi = b_i2s[o];
#pragma unroll
        for (int m = 0; m < 4; m++) {
            int q = q0 + 16 * m;
            float a0, a1, a2, a3;
            {
                int w = t - q;
                a0 = bs + (((unsigned)w < 64u) ? g_i2s[((((b<<6)|q)<<6 | w)<<8) | o] : bi);
                w = t - (q + 1);
                a1 = bs + (((unsigned)w < 64u) ? g_i2s[((((b<<6)|(q+1))<<6 | w)<<8) | o] : bi);
                w = t - (q + 2);
                a2 = bs + (((unsigned)w < 64u) ? g_i2s[((((b<<6)|(q+2))<<6 | w)<<8) | o] : bi);
                w = t - (q + 3);
                a3 = bs + (((unsigned)w < 64u) ? g_i2s[((((b<<6)|(q+3))<<6 | w)<<8) | o] : bi);
            }
            const float* h0 = hsb + m * 320;
#pragma unroll
            for (int k4 = 0; k4 < 16; k4++) {
                float4 vA = *(const float4*)(h0 + 4*k4);
                float4 vB = *(const float4*)(h0 + 64 + 4*k4);
                float4 vC = *(const float4*)(h0 + 128 + 4*k4);
                float4 vD = *(const float4*)(h0 + 192 + 4*k4);
                float4 vE = *(const float4*)(h0 + 256 + 4*k4);
                int k = 4 * k4;
                a0 += vA.x*w0[k] + vB.x*w1[k];  a1 += vB.x*w0[k] + vC.x*w1[k];
                a2 += vC.x*w0[k] + vD.x*w1[k];  a3 += vD.x*w0[k] + vE.x*w1[k];
                a0 += vA.y*w0[k+1] + vB.y*w1[k+1];  a1 += vB.y*w0[k+1] + vC.y*w1[k+1];
                a2 += vC.y*w0[k+1] + vD.y*w1[k+1];  a3 += vD.y*w0[k+1] + vE.y*w1[k+1];
                a0 += vA.z*w0[k+2] + vB.z*w1[k+2];  a1 += vB.z*w0[k+2] + vC.z*w1[k+2];
                a2 += vC.z*w0[k+2] + vD.z*w1[k+2];  a3 += vD.z*w0[k+2] + vE.z*w1[k+2];
                a0 += vA.w*w0[k+3] + vB.w*w1[k+3];  a1 += vB.w*w0[k+3] + vC.w*w1[k+3];
                a2 += vC.w*w0[k+3] + vD.w*w1[k+3];  a3 += vD.w*w0[k+3] + vE.w*w1[k+3];
            }
            gsm[(m*4+0)*256 + o] = sig_(a0);
            gsm[(m*4+1)*256 + o] = sig_(a1);
            gsm[(m*4+2)*256 + o] = sig_(a2);
            gsm[(m*4+3)*256 + o] = sig_(a3);
        }
    }
    __syncthreads();

    // phase 2: c2c + cell/hidden update; 256 threads = 4 row-quads x 64 j
    {
        int j = tid & 63, rq = tid >> 6;
        float wc0[64], wc1[64];
        const float4* wcp = (const float4*)(w_c2c + j * 128);
#pragma unroll
        for (int k2 = 0; k2 < 32; k2++) {
            float4 v = wcp[k2];
            wc0[2*k2] = v.x; wc1[2*k2] = v.y; wc0[2*k2+1] = v.z; wc1[2*k2+1] = v.w;
        }
        float bc = b_c2c[j];
#pragma unroll
        for (int i = 0; i < 4; i++) {
            int rl = rq * 4 + i;
            int r = r0 + rl;
            const float* c0 = csb + rl * 64;  // row r-1 at [0], row r at [64]
            float acc = bc;
#pragma unroll
            for (int k4 = 0; k4 < 16; k4++) {
                float4 vP = *(const float4*)(c0 + 4*k4);
                float4 vQ = *(const float4*)(c0 + 64 + 4*k4);
                int k = 4 * k4;
                acc += vP.x*wc0[k]   + vQ.x*wc1[k];
                acc += vP.y*wc0[k+1] + vQ.y*wc1[k+1];
                acc += vP.z*wc0[k+2] + vQ.z*wc1[k+2];
                acc += vP.w*wc0[k+3] + vQ.w*wc1[k+3];
            }
            int a = rl >> 2;
            int oo = ((rl & 3) << 6) | j;
            float ig = gsm[(0  + a)*256 + oo];
            float gg = gsm[(4  + a)*256 + oo];
            float fg = gsm[(8  + a)*256 + oo];
            float og = gsm[(12 + a)*256 + oo];
            float cv = fg * acc + ig * gg;
            float hv = og * tanhf(cv);
            cdst[r * 64 + j] = cv;
            hdst[r * 64 + j] = hv;
            int w = t - r;
            if ((unsigned)w < 64u)
                g_hbuf[((((b << 6) | r) << 6 | w) << 6) | j] = hv;
        }
    }
}

// up: out[b][oc][r][w] = b_up[oc] + sum_j g_hbuf[b][r][w][j] * w_up[oc][j]
__global__ __launch_bounds__(256) void up_kernel(const float* __restrict__ w_up,
                                                 const float* __restrict__ b_up,
                                                 float* __restrict__ out) {
    __shared__ float hsm[64 * 64];    // [w][j]
    __shared__ float osm[128 * 64];   // [oc][w]
    int b = blockIdx.x >> 6, r = blockIdx.x & 63;
    int tid = threadIdx.x;
    const float* src = g_hbuf + (((b << 6) | r) << 12);
    for (int i = tid; i < 4096; i += 256) hsm[i] = src[i];
    __syncthreads();

    int oc = tid & 127, wh = tid >> 7;
    float u[64];
    const float4* pu = (const float4*)(w_up + (oc << 6));
#pragma unroll
    for (int k4 = 0; k4 < 16; k4++) {
        float4 v = pu[k4];
        u[4*k4] = v.x; u[4*k4+1] = v.y; u[4*k4+2] = v.z; u[4*k4+3] = v.w;
    }
    float bu = b_up[oc];
    for (int w = (wh << 5); w < (wh << 5) + 32; w++) {
        float acc = bu;
        const float* hr = hsm + (w << 6);
#pragma unroll
        for (int k4 = 0; k4 < 16; k4++) {
            float4 v = *(const float4*)(hr + 4*k4);
            int k = 4 * k4;
            acc += v.x*u[k] + v.y*u[k+1] + v.z*u[k+2] + v.w*u[k+3];
        }
        osm[(oc << 6) | w] = acc;
    }
    __syncthreads();

    // coalesced store: consecutive tid -> consecutive w
    float* ob = out + (((b << 7) << 6 | r) << 6);
    for (int i = tid; i < 8192; i += 256) {
        int oc2 = i >> 6, w = i & 63;
        ob[((oc2 << 6) << 6) | w] = osm[i];
    }
}

extern "C" void kernel_launch(void* const* d_in, const int* in_sizes, int n_in,
                              void* d_out, int out_size) {
    const float* inputs = (const float*)d_in[0];
    const float* w_i2s  = (const float*)d_in[1];
    const float* b_i2s  = (const float*)d_in[2];
    const float* w_s2s  = (const float*)d_in[3];
    const float* b_s2s  = (const float*)d_in[4];
    const float* w_c2c  = (const float*)d_in[5];
    const float* b_c2c  = (const float*)d_in[6];
    const float* w_up   = (const float*)d_in[7];
    const float* b_up   = (const float*)d_in[8];
    float* out = (float*)d_out;

    zero_kernel<<<512, 256>>>();
    i2s_kernel<<<2048, 256>>>(inputs, w_i2s, b_i2s);
    for (int t = 0; t < NWD; t++)
        step_kernel<<<128, 256>>>(t, w_s2s, b_s2s, w_c2c, b_c2c, b_i2s);
    up_kernel<<<2048, 256>>>(w_up, b_up, out);
}

// round 3
// speedup vs baseline: 1.6344x; 1.6344x over previous
#include <cuda_runtime.h>

#define BB 32
#define NWD 127

__device__ float g_i2s[BB * 64 * 64 * 256];  // [b][r][w][o] (includes b_i2s)
__device__ float g_hbuf[BB * 64 * 64 * 64];  // [b][r][w][j]
__device__ float g_wcT[2 * 64 * 64];         // [s][k][j] transposed w_c2c

__device__ __forceinline__ float sig_(float x) { return 1.0f / (1.0f + __expf(-x)); }

__device__ __forceinline__ unsigned smem_u32(const void* p) {
    return (unsigned)__cvta_generic_to_shared(p);
}
__device__ __forceinline__ unsigned mapa_rank(unsigned addr, int rank) {
    unsigned r;
    asm("mapa.shared::cluster.u32 %0, %1, %2;" : "=r"(r) : "r"(addr), "r"(rank));
    return r;
}
__device__ __forceinline__ float ldsc(unsigned addr) {
    float v;
    asm volatile("ld.shared::cluster.f32 %0, [%1];" : "=f"(v) : "r"(addr));
    return v;
}
#define CLUSTER_SYNC() do { \
    asm volatile("barrier.cluster.arrive.aligned;" ::: "memory"); \
    asm volatile("barrier.cluster.wait.aligned;" ::: "memory"); \
} while (0)

// transpose w_c2c[j][k][s] -> g_wcT[s][k][j]
__global__ void prep_wc(const float* __restrict__ w_c2c) {
    int i = blockIdx.x * 256 + threadIdx.x;  // 8192
    int s = i >> 12, rest = i & 4095, k = rest >> 6, j = rest & 63;
    g_wcT[s * 4096 + k * 64 + j] = w_c2c[(j * 64 + k) * 2 + s];
}

// i2s: g_i2s[b][r][w][o] = b_i2s[o] + sum_c inputs[b][c][r][w] * w_i2s[o][c]
__global__ __launch_bounds__(256) void i2s_kernel(const float* __restrict__ inputs,
                                                  const float* __restrict__ w_i2s,
                                                  const float* __restrict__ b_i2s) {
    __shared__ float xs[64 * 64];  // [c][w]
    int b = blockIdx.x >> 6, r = blockIdx.x & 63;
    int tid = threadIdx.x;
    for (int i = tid; i < 4096; i += 256) {
        int c = i >> 6, w = i & 63;
        xs[i] = inputs[((((b << 6) | c) << 6 | r) << 6) | w];
    }
    __syncthreads();

    int o = tid & 127, wh = tid >> 7;
    float wa[64], wb[64];
    const float4* pa = (const float4*)(w_i2s + (o << 6));
    const float4* pb = (const float4*)(w_i2s + ((o + 128) << 6));
#pragma unroll
    for (int k4 = 0; k4 < 16; k4++) {
        float4 va = pa[k4], vb = pb[k4];
        wa[4*k4] = va.x; wa[4*k4+1] = va.y; wa[4*k4+2] = va.z; wa[4*k4+3] = va.w;
        wb[4*k4] = vb.x; wb[4*k4+1] = vb.y; wb[4*k4+2] = vb.z; wb[4*k4+3] = vb.w;
    }
    float ba = b_i2s[o], bb = b_i2s[o + 128];
    float* ob = g_i2s + ((((b << 6) | r) << 6) << 8);
    for (int w = (wh << 5); w < (wh << 5) + 32; w++) {
        float a0 = ba, a1 = bb;
#pragma unroll
        for (int k = 0; k < 64; k++) {
            float x = xs[(k << 6) | w];
            a0 += x * wa[k];
            a1 += x * wb[k];
        }
        ob[(w << 8) | o] = a0;
        ob[((w << 8) | o) + 128] = a1;
    }
}

// persistent diagonal scan: 128 CTAs, cluster of 4 = one batch.
__global__ void __cluster_dims__(4, 1, 1) __launch_bounds__(256, 1)
scan_kernel(const float* __restrict__ w_s2s,
            const float* __restrict__ b_s2s,
            const float* __restrict__ b_c2c,
            const float* __restrict__ b_i2s) {
    __shared__ __align__(16) float h_st[2][1024];  // own 16 rows, double-buffered
    __shared__ __align__(16) float c_st[2][1024];
    __shared__ __align__(16) float hsb[1280];      // 4 bands x rows q-1..q+3
    __shared__ __align__(16) float cprev[64];      // c row r0-1
    __shared__ __align__(16) float gsm[4096];      // gates [16][256]

    int b = blockIdx.x >> 2, rg = blockIdx.x & 3;
    int r0 = rg << 4, q0 = rg << 2;
    int tid = threadIdx.x;
    int j = tid & 63, rq = tid >> 6;

    // persistent weights: w_s2s row o=tid
    float w0[64], w1[64];
    {
        const float4* wp = (const float4*)(w_s2s + tid * 128);
#pragma unroll
        for (int k2 = 0; k2 < 32; k2++) {
            float4 v = wp[k2];
            w0[2*k2] = v.x; w1[2*k2] = v.y; w0[2*k2+1] = v.z; w1[2*k2+1] = v.w;
        }
    }
    float bs = b_s2s[tid], bi = b_i2s[tid];
    float bcj = b_c2c[j];

    // zero initial state buffer 0
    for (int i = tid; i < 1024; i += 256) { h_st[0][i] = 0.f; c_st[0][i] = 0.f; }

    unsigned h_base = smem_u32(h_st);
    unsigned c_base = smem_u32(c_st);
    unsigned h_rank[4];
#pragma unroll
    for (int rk = 0; rk < 4; rk++) h_rank[rk] = mapa_rank(h_base, rk);
    unsigned cprev_base = (rg > 0) ? mapa_rank(c_base, rg - 1) : 0u;

    const float* wc0p = g_wcT + j;
    const float* wc1p = g_wcT + 4096 + j;

    for (int t = 0; t < NWD; t++) {
        int p = t & 1;

        // prefetch i2s values for this step (hide DRAM behind the cluster barrier)
        float xi[16];
#pragma unroll
        for (int m = 0; m < 4; m++)
#pragma unroll
            for (int i = 0; i < 4; i++) {
                int row = q0 + 16 * m + i;
                int w = t - row;
                xi[m*4+i] = ((unsigned)w < 64u)
                    ? g_i2s[((((b << 6) | row) << 6 | w) << 8) | tid] : bi;
            }

        CLUSTER_SYNC();  // state buf[p] from step t-1 now visible cluster-wide

        // stage h rows (bands) via DSMEM
        for (int i = tid; i < 1280; i += 256) {
            int m = i / 320, ii = (i >> 6) % 5, k = i & 63;
            int row = q0 + 16 * m - 1 + ii;
            float v = 0.f;
            if (row >= 0) {
                int owner = row >> 4, lr = row & 15;
                v = ldsc(h_rank[owner] + ((p << 10) + lr * 64 + k) * 4);
            }
            hsb[i] = v;
        }
        // stage c row r0-1
        if (tid < 64) {
            float v = 0.f;
            if (rg > 0) v = ldsc(cprev_base + ((p << 10) + 15 * 64 + tid) * 4);
            cprev[tid] = v;
        }
        __syncthreads();

        // phase 1: 16 gate rows x 256 outputs
#pragma unroll
        for (int m = 0; m < 4; m++) {
            float a0 = bs + xi[m*4+0];
            float a1 = bs + xi[m*4+1];
            float a2 = bs + xi[m*4+2];
            float a3 = bs + xi[m*4+3];
            const float* h0 = hsb + m * 320;
#pragma unroll
            for (int k4 = 0; k4 < 16; k4++) {
                float4 vA = *(const float4*)(h0 + 4*k4);
                float4 vB = *(const float4*)(h0 + 64 + 4*k4);
                float4 vC = *(const float4*)(h0 + 128 + 4*k4);
                float4 vD = *(const float4*)(h0 + 192 + 4*k4);
                float4 vE = *(const float4*)(h0 + 256 + 4*k4);
                int k = 4 * k4;
                a0 += vA.x*w0[k] + vB.x*w1[k];      a1 += vB.x*w0[k] + vC.x*w1[k];
                a2 += vC.x*w0[k] + vD.x*w1[k];      a3 += vD.x*w0[k] + vE.x*w1[k];
                a0 += vA.y*w0[k+1] + vB.y*w1[k+1];  a1 += vB.y*w0[k+1] + vC.y*w1[k+1];
                a2 += vC.y*w0[k+1] + vD.y*w1[k+1];  a3 += vD.y*w0[k+1] + vE.y*w1[k+1];
                a0 += vA.z*w0[k+2] + vB.z*w1[k+2];  a1 += vB.z*w0[k+2] + vC.z*w1[k+2];
                a2 += vC.z*w0[k+2] + vD.z*w1[k+2];  a3 += vD.z*w0[k+2] + vE.z*w1[k+2];
                a0 += vA.w*w0[k+3] + vB.w*w1[k+3];  a1 += vB.w*w0[k+3] + vC.w*w1[k+3];
                a2 += vC.w*w0[k+3] + vD.w*w1[k+3];  a3 += vD.w*w0[k+3] + vE.w*w1[k+3];
            }
            gsm[(m*4+0)*256 + tid] = sig_(a0);
            gsm[(m*4+1)*256 + tid] = sig_(a1);
            gsm[(m*4+2)*256 + tid] = sig_(a2);
            gsm[(m*4+3)*256 + tid] = sig_(a3);
        }
        __syncthreads();

        // phase 2: c2c + cell/hidden update; thread = (row-quad rq, j)
        {
            int rl0 = rq * 4;
            const float* rowm1 = (rl0 == 0) ? cprev : &c_st[p][(rl0 - 1) * 64];
            const float* row0v = &c_st[p][(rl0 + 0) * 64];
            const float* row1v = &c_st[p][(rl0 + 1) * 64];
            const float* row2v = &c_st[p][(rl0 + 2) * 64];
            const float* row3v = &c_st[p][(rl0 + 3) * 64];
            float acc0 = bcj, acc1 = bcj, acc2 = bcj, acc3 = bcj;
#pragma unroll
            for (int k = 0; k < 64; k++) {
                float wk0 = wc0p[k * 64];
                float wk1 = wc1p[k * 64];
                float cm = rowm1[k], c0v = row0v[k], c1v = row1v[k];
                float c2v = row2v[k], c3v = row3v[k];
                acc0 += cm  * wk0 + c0v * wk1;
                acc1 += c0v * wk0 + c1v * wk1;
                acc2 += c1v * wk0 + c2v * wk1;
                acc3 += c2v * wk0 + c3v * wk1;
            }
            float accs[4] = {acc0, acc1, acc2, acc3};
#pragma unroll
            for (int i = 0; i < 4; i++) {
                int rl = rl0 + i;
                int r = r0 + rl;
                int oo = (i << 6) | j;
                float ig = gsm[(0  + rq) * 256 + oo];
                float gg = gsm[(4  + rq) * 256 + oo];
                float fg = gsm[(8  + rq) * 256 + oo];
                float og = gsm[(12 + rq) * 256 + oo];
                float cv = fg * accs[i] + ig * gg;
                float hv = og * tanhf(cv);
                c_st[1 - p][rl * 64 + j] = cv;
                h_st[1 - p][rl * 64 + j] = hv;
                int w = t - r;
                if ((unsigned)w < 64u)
                    g_hbuf[((((b << 6) | r) << 6 | w) << 6) | j] = hv;
            }
        }
        // next iteration's CLUSTER_SYNC is the full barrier before reuse
    }
}

// up: out[b][oc][r][w] = b_up[oc] + sum_j g_hbuf[b][r][w][j] * w_up[oc][j]
__global__ __launch_bounds__(256) void up_kernel(const float* __restrict__ w_up,
                                                 const float* __restrict__ b_up,
                                                 float* __restrict__ out) {
    __shared__ float hsm[64 * 64];
    __shared__ float osm[128 * 64];
    int b = blockIdx.x >> 6, r = blockIdx.x & 63;
    int tid = threadIdx.x;
    const float* src = g_hbuf + (((b << 6) | r) << 12);
    for (int i = tid; i < 4096; i += 256) hsm[i] = src[i];
    __syncthreads();

    int oc = tid & 127, wh = tid >> 7;
    float u[64];
    const float4* pu = (const float4*)(w_up + (oc << 6));
#pragma unroll
    for (int k4 = 0; k4 < 16; k4++) {
        float4 v = pu[k4];
        u[4*k4] = v.x; u[4*k4+1] = v.y; u[4*k4+2] = v.z; u[4*k4+3] = v.w;
    }
    float bu = b_up[oc];
    for (int w = (wh << 5); w < (wh << 5) + 32; w++) {
        float acc = bu;
        const float* hr = hsm + (w << 6);
#pragma unroll
        for (int k4 = 0; k4 < 16; k4++) {
            float4 v = *(const float4*)(hr + 4*k4);
            int k = 4 * k4;
            acc += v.x*u[k] + v.y*u[k+1] + v.z*u[k+2] + v.w*u[k+3];
        }
        osm[(oc << 6) | w] = acc;
    }
    __syncthreads();

    float* ob = out + (((b << 7) << 6 | r) << 6);
    for (int i = tid; i < 8192; i += 256) {
        int oc2 = i >> 6, w = i & 63;
        ob[((oc2 << 6) << 6) | w] = osm[i];
    }
}

extern "C" void kernel_launch(void* const* d_in, const int* in_sizes, int n_in,
                              void* d_out, int out_size) {
    const float* inputs = (const float*)d_in[0];
    const float* w_i2s  = (const float*)d_in[1];
    const float* b_i2s  = (const float*)d_in[2];
    const float* w_s2s  = (const float*)d_in[3];
    const float* b_s2s  = (const float*)d_in[4];
    const float* w_c2c  = (const float*)d_in[5];
    const float* b_c2c  = (const float*)d_in[6];
    const float* w_up   = (const float*)d_in[7];
    const float* b_up   = (const float*)d_in[8];
    float* out = (float*)d_out;

    prep_wc<<<32, 256>>>(w_c2c);
    i2s_kernel<<<2048, 256>>>(inputs, w_i2s, b_i2s);
    scan_kernel<<<128, 256>>>(w_s2s, b_s2s, b_c2c, b_i2s);
    up_kernel<<<2048, 256>>>(w_up, b_up, out);
}

// round 4
// speedup vs baseline: 2.1047x; 1.2878x over previous
#include <cuda_runtime.h>

#define BB 32
#define NWD 127

__device__ float g_i2s[BB * 64 * 64 * 256];  // [b][r][w][o] (includes b_i2s)
__device__ float g_hbuf[BB * 64 * 64 * 64];  // [b][r][w][j]

typedef unsigned long long u64t;

__device__ __forceinline__ float sig_(float x) { return 1.0f / (1.0f + __expf(-x)); }
__device__ __forceinline__ float tanh_(float x) {
    float e = __expf(-2.0f * x);
    return __fdividef(1.0f - e, 1.0f + e);
}
__device__ __forceinline__ u64t pk(float lo, float hi) {
    u64t r; asm("mov.b64 %0, {%1,%2};" : "=l"(r) : "f"(lo), "f"(hi)); return r;
}
__device__ __forceinline__ float2 upk(u64t v) {
    float2 r; asm("mov.b64 {%0,%1}, %2;" : "=f"(r.x), "=f"(r.y) : "l"(v)); return r;
}
__device__ __forceinline__ void fma2(u64t& d, u64t a, u64t b) {
    asm("fma.rn.f32x2 %0, %1, %2, %0;" : "+l"(d) : "l"(a), "l"(b));
}
__device__ __forceinline__ void lds2(u64t& a, u64t& b, unsigned addr) {
    asm volatile("ld.shared.v2.u64 {%0,%1}, [%2];" : "=l"(a), "=l"(b) : "r"(addr));
}
__device__ __forceinline__ u64t lds1(unsigned addr) {
    u64t a; asm volatile("ld.shared.u64 %0, [%1];" : "=l"(a) : "r"(addr)); return a;
}
__device__ __forceinline__ unsigned smem_u32(const void* p) {
    return (unsigned)__cvta_generic_to_shared(p);
}
__device__ __forceinline__ unsigned mapa_rank(unsigned addr, int rank) {
    unsigned r;
    asm("mapa.shared::cluster.u32 %0, %1, %2;" : "=r"(r) : "r"(addr), "r"(rank));
    return r;
}
__device__ __forceinline__ float ldsc(unsigned addr) {
    float v;
    asm volatile("ld.shared::cluster.f32 %0, [%1];" : "=f"(v) : "r"(addr));
    return v;
}
#define CLUSTER_SYNC() do { \
    asm volatile("barrier.cluster.arrive.aligned;" ::: "memory"); \
    asm volatile("barrier.cluster.wait.aligned;" ::: "memory"); \
} while (0)

// ---------------------------------------------------------------------------
// i2s: g_i2s[b][r][w][o] = b_i2s[o] + sum_c inputs[b][c][r][w] * w_i2s[o][c]
// ---------------------------------------------------------------------------
__global__ __launch_bounds__(256) void i2s_kernel(const float* __restrict__ inputs,
                                                  const float* __restrict__ w_i2s,
                                                  const float* __restrict__ b_i2s) {
    __shared__ float xs[64 * 64];  // [c][w]
    int b = blockIdx.x >> 6, r = blockIdx.x & 63;
    int tid = threadIdx.x;
    for (int i = tid; i < 4096; i += 256) {
        int c = i >> 6, w = i & 63;
        xs[i] = inputs[((((b << 6) | c) << 6 | r) << 6) | w];
    }
    __syncthreads();

    int o = tid & 127, wh = tid >> 7;
    float wa[64], wb[64];
    const float4* pa = (const float4*)(w_i2s + (o << 6));
    const float4* pb = (const float4*)(w_i2s + ((o + 128) << 6));
#pragma unroll
    for (int k4 = 0; k4 < 16; k4++) {
        float4 va = pa[k4], vb = pb[k4];
        wa[4*k4] = va.x; wa[4*k4+1] = va.y; wa[4*k4+2] = va.z; wa[4*k4+3] = va.w;
        wb[4*k4] = vb.x; wb[4*k4+1] = vb.y; wb[4*k4+2] = vb.z; wb[4*k4+3] = vb.w;
    }
    float ba = b_i2s[o], bb = b_i2s[o + 128];
    float* ob = g_i2s + ((((b << 6) | r) << 6) << 8);
    for (int w = (wh << 5); w < (wh << 5) + 32; w++) {
        float a0 = ba, a1 = bb;
#pragma unroll
        for (int k = 0; k < 64; k++) {
            float x = xs[(k << 6) | w];
            a0 += x * wa[k];
            a1 += x * wb[k];
        }
        ob[(w << 8) | o] = a0;
        ob[((w << 8) | o) + 128] = a1;
    }
}

// ---------------------------------------------------------------------------
// persistent diagonal scan: 128 CTAs, cluster of 4 = one batch.
// dynamic smem layout (float offsets):
//   h_st   @ 0     (2 x 1024)
//   c_st   @ 2048  (2 x 1024)
//   hsb    @ 4096  (1280)   4 bands x rows q-1..q+3
//   cprev  @ 5376  (64)
//   gsm    @ 5440  (4096)   [16][256]
//   wcs    @ 9536  (8192)   [s][kp][j][2]  packed w_c2c pairs
// total 17728 floats = 70912 B
// ---------------------------------------------------------------------------
#define OF_H    0
#define OF_C    2048
#define OF_HSB  4096
#define OF_CPR  5376
#define OF_GSM  5440
#define OF_WCS  9536
#define SCAN_SMEM_BYTES (17728 * 4)

__global__ void __cluster_dims__(4, 1, 1) __launch_bounds__(256, 1)
scan_kernel(const float* __restrict__ w_s2s,
            const float* __restrict__ b_s2s,
            const float* __restrict__ w_c2c,
            const float* __restrict__ b_c2c,
            const float* __restrict__ b_i2s) {
    extern __shared__ float smp[];
    unsigned sbase = smem_u32(smp);

    int b = blockIdx.x >> 2, rg = blockIdx.x & 3;
    int r0 = rg << 4, q0 = rg << 2;
    int tid = threadIdx.x;
    int j = tid & 63, rq = tid >> 6;

    // persistent s2s weights, packed as k-pairs
    u64t wp0[32], wp1[32];
    {
        const float4* wp = (const float4*)(w_s2s + tid * 128);
#pragma unroll
        for (int k2 = 0; k2 < 32; k2++) {
            float4 v = wp[k2];
            wp0[k2] = pk(v.x, v.z);  // (w0[2k2], w0[2k2+1])
            wp1[k2] = pk(v.y, v.w);  // (w1[2k2], w1[2k2+1])
        }
    }
    float bs = b_s2s[tid], bi = b_i2s[tid];
    float bcj = b_c2c[j];

    // build packed w_c2c in smem: wcs[s][kp][j][e] = w_c2c[j][2kp+e][s]
    for (int i = tid; i < 8192; i += 256) {
        int s = i >> 12, rr = i & 4095, kp = rr >> 7, q = rr & 127, jj = q >> 1, e = q & 1;
        smp[OF_WCS + i] = w_c2c[(((jj << 6) + 2 * kp + e) << 1) + s];
    }
    // zero initial state buffer 0
    for (int i = tid; i < 1024; i += 256) { smp[OF_H + i] = 0.f; smp[OF_C + i] = 0.f; }

    unsigned h_rank[4];
#pragma unroll
    for (int rk = 0; rk < 4; rk++) h_rank[rk] = mapa_rank(sbase + OF_H * 4, rk);
    unsigned cprev_base = (rg > 0) ? mapa_rank(sbase + OF_C * 4, rg - 1) : 0u;

    for (int t = 0; t < NWD; t++) {
        int p = t & 1;

        // prefetch i2s for this step (hidden behind cluster barrier)
        float xi[16];
#pragma unroll
        for (int m = 0; m < 4; m++)
#pragma unroll
            for (int i = 0; i < 4; i++) {
                int row = q0 + 16 * m + i;
                int w = t - row;
                xi[m*4+i] = ((unsigned)w < 64u)
                    ? g_i2s[((((b << 6) | row) << 6 | w) << 8) | tid] : bi;
            }

        CLUSTER_SYNC();  // buf[p] from step t-1 visible cluster-wide

        // stage h bands via DSMEM
        for (int i = tid; i < 1280; i += 256) {
            int m = i / 320, ii = (i >> 6) % 5, k = i & 63;
            int row = q0 + 16 * m - 1 + ii;
            float v = 0.f;
            if (row >= 0) {
                int owner = row >> 4, lr = row & 15;
                v = ldsc(h_rank[owner] + ((p << 10) + lr * 64 + k) * 4);
            }
            smp[OF_HSB + i] = v;
        }
        if (tid < 64) {
            float v = 0.f;
            if (rg > 0) v = ldsc(cprev_base + ((p << 10) + 960 + tid) * 4);
            smp[OF_CPR + tid] = v;
        }
        __syncthreads();

        // ---- phase 1: 16 gate rows x 256 outputs, packed f32x2 ----
#pragma unroll
        for (int m = 0; m < 4; m++) {
            u64t a0 = pk(bs + xi[m*4+0], 0.f);
            u64t a1 = pk(bs + xi[m*4+1], 0.f);
            u64t a2 = pk(bs + xi[m*4+2], 0.f);
            u64t a3 = pk(bs + xi[m*4+3], 0.f);
            unsigned hb = sbase + (OF_HSB + m * 320) * 4;
#pragma unroll
            for (int k4 = 0; k4 < 16; k4++) {
                u64t A0,A1,B0,B1,C0,C1,D0,D1,E0,E1;
                lds2(A0, A1, hb + k4*16);
                lds2(B0, B1, hb + 256 + k4*16);
                lds2(C0, C1, hb + 512 + k4*16);
                lds2(D0, D1, hb + 768 + k4*16);
                lds2(E0, E1, hb + 1024 + k4*16);
                int kp = 2 * k4;
                fma2(a0, A0, wp0[kp]);   fma2(a0, B0, wp1[kp]);
                fma2(a1, B0, wp0[kp]);   fma2(a1, C0, wp1[kp]);
                fma2(a2, C0, wp0[kp]);   fma2(a2, D0, wp1[kp]);
                fma2(a3, D0, wp0[kp]);   fma2(a3, E0, wp1[kp]);
                fma2(a0, A1, wp0[kp+1]); fma2(a0, B1, wp1[kp+1]);
                fma2(a1, B1, wp0[kp+1]); fma2(a1, C1, wp1[kp+1]);
                fma2(a2, C1, wp0[kp+1]); fma2(a2, D1, wp1[kp+1]);
                fma2(a3, D1, wp0[kp+1]); fma2(a3, E1, wp1[kp+1]);
            }
            float2 u0 = upk(a0), u1 = upk(a1), u2 = upk(a2), u3 = upk(a3);
            smp[OF_GSM + (m*4+0)*256 + tid] = sig_(u0.x + u0.y);
            smp[OF_GSM + (m*4+1)*256 + tid] = sig_(u1.x + u1.y);
            smp[OF_GSM + (m*4+2)*256 + tid] = sig_(u2.x + u2.y);
            smp[OF_GSM + (m*4+3)*256 + tid] = sig_(u3.x + u3.y);
        }
        __syncthreads();

        // ---- phase 2: c2c + cell/hidden update, packed f32x2 ----
        {
            int rl0 = rq * 4;
            unsigned cb = sbase + (OF_C + (p << 10)) * 4;
            unsigned a_m1 = (rl0 == 0) ? (sbase + OF_CPR * 4) : (cb + (rl0 - 1) * 256);
            unsigned a_0 = cb + rl0 * 256;
            unsigned wcb0 = sbase + OF_WCS * 4 + j * 8;
            unsigned wcb1 = wcb0 + 4096 * 4;
            u64t ac0 = pk(bcj, 0.f), ac1 = ac0, ac2 = ac0, ac3 = ac0;
#pragma unroll
            for (int k4 = 0; k4 < 16; k4++) {
                u64t m0,m1, r00,r01, r10,r11, r20,r21, r30,r31;
                lds2(m0,  m1,  a_m1 + k4*16);
                lds2(r00, r01, a_0 + k4*16);
                lds2(r10, r11, a_0 + 256 + k4*16);
                lds2(r20, r21, a_0 + 512 + k4*16);
                lds2(r30, r31, a_0 + 768 + k4*16);
                int kp = 2 * k4;
                u64t w00 = lds1(wcb0 + kp*512);
                u64t w01 = lds1(wcb0 + kp*512 + 512);
                u64t w10 = lds1(wcb1 + kp*512);
                u64t w11 = lds1(wcb1 + kp*512 + 512);
                fma2(ac0, m0,  w00); fma2(ac0, r00, w10);
                fma2(ac1, r00, w00); fma2(ac1, r10, w10);
                fma2(ac2, r10, w00); fma2(ac2, r20, w10);
                fma2(ac3, r20, w00); fma2(ac3, r30, w10);
                fma2(ac0, m1,  w01); fma2(ac0, r01, w11);
                fma2(ac1, r01, w01); fma2(ac1, r11, w11);
                fma2(ac2, r11, w01); fma2(ac2, r21, w11);
                fma2(ac3, r21, w01); fma2(ac3, r31, w11);
            }
            float2 f0 = upk(ac0), f1 = upk(ac1), f2 = upk(ac2), f3 = upk(ac3);
            float accs[4] = {f0.x + f0.y, f1.x + f1.y, f2.x + f2.y, f3.x + f3.y};
#pragma unroll
            for (int i = 0; i < 4; i++) {
                int rl = rl0 + i;
                int r = r0 + rl;
                int oo = (i << 6) | j;
                float ig = smp[OF_GSM + (0  + rq)*256 + oo];
                float gg = smp[OF_GSM + (4  + rq)*256 + oo];
                float fg = smp[OF_GSM + (8  + rq)*256 + oo];
                float og = smp[OF_GSM + (12 + rq)*256 + oo];
                float cv = fg * accs[i] + ig * gg;
                float hv = og * tanh_(cv);
                smp[OF_C + ((1 - p) << 10) + rl * 64 + j] = cv;
                smp[OF_H + ((1 - p) << 10) + rl * 64 + j] = hv;
                int w = t - r;
                if ((unsigned)w < 64u)
                    g_hbuf[((((b << 6) | r) << 6 | w) << 6) | j] = hv;
            }
        }
    }
}

// ---------------------------------------------------------------------------
// up: out[b][oc][r][w] = b_up[oc] + sum_j g_hbuf[b][r][w][j] * w_up[oc][j]
// dynamic smem: hsm @ 0 (4096), osm @ 4096 ([128][65])
// ---------------------------------------------------------------------------
#define UP_SMEM_BYTES ((4096 + 128 * 65) * 4)

__global__ __launch_bounds__(256) void up_kernel(const float* __restrict__ w_up,
                                                 const float* __restrict__ b_up,
                                                 float* __restrict__ out) {
    extern __shared__ float us[];
    float* hsm = us;
    float* osm = us + 4096;
    unsigned hbase = smem_u32(us);
    int b = blockIdx.x >> 6, r = blockIdx.x & 63;
    int tid = threadIdx.x;
    const float* src = g_hbuf + (((b << 6) | r) << 12);
    for (int i = tid; i < 4096; i += 256) hsm[i] = src[i];
    __syncthreads();

    int oc = tid & 127, wh = tid >> 7;
    u64t uu[32];
    const float4* pu = (const float4*)(w_up + (oc << 6));
#pragma unroll
    for (int k4 = 0; k4 < 16; k4++) {
        float4 v = pu[k4];
        uu[2*k4]     = pk(v.x, v.y);
        uu[2*k4 + 1] = pk(v.z, v.w);
    }
    float bu = b_up[oc];
    for (int w = (wh << 5); w < (wh << 5) + 32; w++) {
        u64t a = pk(bu, 0.f);
        unsigned hr = hbase + (w << 8);
#pragma unroll
        for (int k4 = 0; k4 < 16; k4++) {
            u64t x0, x1;
            lds2(x0, x1, hr + k4*16);
            fma2(a, x0, uu[2*k4]);
            fma2(a, x1, uu[2*k4 + 1]);
        }
        float2 f = upk(a);
        osm[oc * 65 + w] = f.x + f.y;  // pitch 65: conflict-free
    }
    __syncthreads();

    float* ob = out + (((b << 7) << 6 | r) << 6);
    for (int i = tid; i < 8192; i += 256) {
        int oc2 = i >> 6, w = i & 63;
        ob[(oc2 << 12) | w] = osm[oc2 * 65 + w];
    }
}

extern "C" void kernel_launch(void* const* d_in, const int* in_sizes, int n_in,
                              void* d_out, int out_size) {
    const float* inputs = (const float*)d_in[0];
    const float* w_i2s  = (const float*)d_in[1];
    const float* b_i2s  = (const float*)d_in[2];
    const float* w_s2s  = (const float*)d_in[3];
    const float* b_s2s  = (const float*)d_in[4];
    const float* w_c2c  = (const float*)d_in[5];
    const float* b_c2c  = (const float*)d_in[6];
    const float* w_up   = (const float*)d_in[7];
    const float* b_up   = (const float*)d_in[8];
    float* out = (float*)d_out;

    cudaFuncSetAttribute(scan_kernel, cudaFuncAttributeMaxDynamicSharedMemorySize, SCAN_SMEM_BYTES);
    cudaFuncSetAttribute(up_kernel, cudaFuncAttributeMaxDynamicSharedMemorySize, UP_SMEM_BYTES);

    i2s_kernel<<<2048, 256>>>(inputs, w_i2s, b_i2s);
    scan_kernel<<<128, 256, SCAN_SMEM_BYTES>>>(w_s2s, b_s2s, w_c2c, b_c2c, b_i2s);
    up_kernel<<<2048, 256, UP_SMEM_BYTES>>>(w_up, b_up, out);
}

// round 6
// speedup vs baseline: 2.2541x; 1.0710x over previous
#include <cuda_runtime.h>

#define BB 32
#define NWD 127

__device__ float g_i2s[BB * 64 * 64 * 256];  // [b][r][w][o] (includes b_i2s)
__device__ float g_hbuf[BB * 64 * 64 * 64];  // [b][r][w][j]

typedef unsigned long long u64t;

__device__ __forceinline__ float sig_(float x) { return 1.0f / (1.0f + __expf(-x)); }
__device__ __forceinline__ float tanh_(float x) {
    float e = __expf(-2.0f * x);
    return __fdividef(1.0f - e, 1.0f + e);
}
__device__ __forceinline__ u64t pk(float lo, float hi) {
    u64t r; asm("mov.b64 %0, {%1,%2};" : "=l"(r) : "f"(lo), "f"(hi)); return r;
}
__device__ __forceinline__ float2 upk(u64t v) {
    float2 r; asm("mov.b64 {%0,%1}, %2;" : "=f"(r.x), "=f"(r.y) : "l"(v)); return r;
}
__device__ __forceinline__ void fma2(u64t& d, u64t a, u64t b) {
    asm("fma.rn.f32x2 %0, %1, %2, %0;" : "+l"(d) : "l"(a), "l"(b));
}
__device__ __forceinline__ void lds2(u64t& a, u64t& b, unsigned addr) {
    asm volatile("ld.shared.v2.u64 {%0,%1}, [%2];" : "=l"(a), "=l"(b) : "r"(addr));
}
__device__ __forceinline__ u64t lds1(unsigned addr) {
    u64t a; asm volatile("ld.shared.u64 %0, [%1];" : "=l"(a) : "r"(addr)); return a;
}
__device__ __forceinline__ unsigned smem_u32(const void* p) {
    return (unsigned)__cvta_generic_to_shared(p);
}
__device__ __forceinline__ unsigned mapa_rank(unsigned addr, int rank) {
    unsigned r;
    asm("mapa.shared::cluster.u32 %0, %1, %2;" : "=r"(r) : "r"(addr), "r"(rank));
    return r;
}
__device__ __forceinline__ void stsc(unsigned addr, float v) {
    asm volatile("st.shared::cluster.f32 [%0], %1;" :: "r"(addr), "f"(v) : "memory");
}
#define CLUSTER_SYNC() do { \
    asm volatile("barrier.cluster.arrive.aligned;" ::: "memory"); \
    asm volatile("barrier.cluster.wait.aligned;" ::: "memory"); \
} while (0)

// ---------------------------------------------------------------------------
// i2s: g_i2s[b][r][w][o] = b_i2s[o] + sum_c inputs[b][c][r][w] * w_i2s[o][c]
// f32x2: acc lanes = (o, o+128); x pre-duplicated in smem [k][w] as pk(x,x).
// ---------------------------------------------------------------------------
__global__ __launch_bounds__(256) void i2s_kernel(const float* __restrict__ inputs,
                                                  const float* __restrict__ w_i2s,
                                                  const float* __restrict__ b_i2s) {
    __shared__ u64t xs2[64 * 64];  // [k][w], each entry = pk(x, x)
    int b = blockIdx.x >> 6, r = blockIdx.x & 63;
    int tid = threadIdx.x;
    for (int i = tid; i < 4096; i += 256) {
        int c = i >> 6, w = i & 63;
        float x = inputs[((((b << 6) | c) << 6 | r) << 6) | w];
        xs2[(c << 6) | w] = pk(x, x);
    }
    __syncthreads();

    int o = tid & 127, wh = tid >> 7;
    u64t wv[64];  // pk(w_i2s[o][k], w_i2s[o+128][k])
    {
        const float4* pa = (const float4*)(w_i2s + (o << 6));
        const float4* pb = (const float4*)(w_i2s + ((o + 128) << 6));
#pragma unroll
        for (int k4 = 0; k4 < 16; k4++) {
            float4 va = pa[k4], vb = pb[k4];
            wv[4*k4]   = pk(va.x, vb.x);
            wv[4*k4+1] = pk(va.y, vb.y);
            wv[4*k4+2] = pk(va.z, vb.z);
            wv[4*k4+3] = pk(va.w, vb.w);
        }
    }
    u64t binit = pk(b_i2s[o], b_i2s[o + 128]);
    float* ob = g_i2s + ((((b << 6) | r) << 6) << 8);
    unsigned xb0 = smem_u32(xs2);

#pragma unroll 1
    for (int g = 0; g < 8; g++) {
        int w0 = (wh << 5) + (g << 2);
        unsigned xb = xb0 + w0 * 8;
        u64t a0 = binit, a1 = binit, a2 = binit, a3 = binit;
#pragma unroll
        for (int k = 0; k < 64; k++) {
            u64t x0, x1, x2, x3;
            lds2(x0, x1, xb + k * 512);
            lds2(x2, x3, xb + k * 512 + 16);
            fma2(a0, x0, wv[k]);
            fma2(a1, x1, wv[k]);
            fma2(a2, x2, wv[k]);
            fma2(a3, x3, wv[k]);
        }
        float2 f0 = upk(a0), f1 = upk(a1), f2 = upk(a2), f3 = upk(a3);
        ob[((w0 + 0) << 8) | o] = f0.x;  ob[(((w0 + 0) << 8) | o) + 128] = f0.y;
        ob[((w0 + 1) << 8) | o] = f1.x;  ob[(((w0 + 1) << 8) | o) + 128] = f1.y;
        ob[((w0 + 2) << 8) | o] = f2.x;  ob[(((w0 + 2) << 8) | o) + 128] = f2.y;
        ob[((w0 + 3) << 8) | o] = f3.x;  ob[(((w0 + 3) << 8) | o) + 128] = f3.y;
    }
}

// ---------------------------------------------------------------------------
// persistent diagonal scan: 128 CTAs, cluster of 4 = one batch.
// producer-push halo via st.shared::cluster; cluster barrier = release/acquire.
// TRAILING CLUSTER_SYNC prevents the exit race (push to retired CTA faults).
// ---------------------------------------------------------------------------
#define OF_C    0
#define OF_HS   2048
#define OF_CS   4608
#define OF_GSM  4736
#define OF_WCS  8832
#define SCAN_SMEM_BYTES (17024 * 4)

__global__ void __cluster_dims__(4, 1, 1) __launch_bounds__(256, 1)
scan_kernel(const float* __restrict__ w_s2s,
            const float* __restrict__ b_s2s,
            const float* __restrict__ w_c2c,
            const float* __restrict__ b_c2c,
            const float* __restrict__ b_i2s) {
    extern __shared__ float smp[];
    unsigned sbase = smem_u32(smp);

    int b = blockIdx.x >> 2, rg = blockIdx.x & 3;
    int r0 = rg << 4, q0 = rg << 2;
    int tid = threadIdx.x;
    int j = tid & 63, rq = tid >> 6;

    // persistent s2s weights, packed as k-pairs
    u64t wp0[32], wp1[32];
    {
        const float4* wp = (const float4*)(w_s2s + tid * 128);
#pragma unroll
        for (int k2 = 0; k2 < 32; k2++) {
            float4 v = wp[k2];
            wp0[k2] = pk(v.x, v.z);
            wp1[k2] = pk(v.y, v.w);
        }
    }
    float bs = b_s2s[tid], bi = b_i2s[tid];
    float bcj = b_c2c[j];

    // packed w_c2c in smem: wcs[s][kp][j][e] = w_c2c[j][2kp+e][s]
    for (int i = tid; i < 8192; i += 256) {
        int s = i >> 12, rr = i & 4095, kp = rr >> 7, q = rr & 127, jj = q >> 1, e = q & 1;
        smp[OF_WCS + i] = w_c2c[(((jj << 6) + 2 * kp + e) << 1) + s];
    }
    // zero state/staging (both parities)
    for (int i = tid; i < 1024; i += 256) smp[OF_C + i] = 0.f;
    for (int i = tid; i < 2560; i += 256) smp[OF_HS + i] = 0.f;
    if (tid < 128) smp[OF_CS + tid] = 0.f;

    // precompute push targets: row r -> consumer (rg', band m', slot ii')
    unsigned htg[4][2];
    unsigned ctg = 0;
#pragma unroll
    for (int i = 0; i < 4; i++) {
        int r = r0 + rq * 4 + i;
        htg[i][0] = 0; htg[i][1] = 0;
        int n = 0;
#pragma unroll
        for (int rg2 = 0; rg2 < 4; rg2++) {
            int v = r + 1 - 4 * rg2;
            if (v >= 0) {
                int mm = v >> 4, ii = v & 15;
                if (mm < 4 && ii < 5)
                    htg[i][n++] = mapa_rank(sbase + OF_HS * 4, rg2)
                                  + ((mm * 5 + ii) * 64 + j) * 4;
            }
        }
    }
    if (rq == 3 && rg < 3) ctg = mapa_rank(sbase + OF_CS * 4, rg + 1) + j * 4;

    for (int t = 0; t < NWD; t++) {
        int p = t & 1, np = 1 - p;

        // prefetch i2s for this step (hidden behind cluster barrier)
        float xi[16];
#pragma unroll
        for (int m = 0; m < 4; m++)
#pragma unroll
            for (int i = 0; i < 4; i++) {
                int row = q0 + 16 * m + i;
                int w = t - row;
                xi[m*4+i] = ((unsigned)w < 64u)
                    ? g_i2s[((((b << 6) | row) << 6 | w) << 8) | tid] : bi;
            }

        CLUSTER_SYNC();  // pushes from step t-1 visible; stage[p] ready

        // ---- phase 1: 16 gate rows x 256 outputs, f32x2 ----
#pragma unroll
        for (int m = 0; m < 4; m++) {
            u64t a0 = pk(bs + xi[m*4+0], 0.f);
            u64t a1 = pk(bs + xi[m*4+1], 0.f);
            u64t a2 = pk(bs + xi[m*4+2], 0.f);
            u64t a3 = pk(bs + xi[m*4+3], 0.f);
            unsigned hb = sbase + (OF_HS + p * 1280 + m * 320) * 4;
#pragma unroll
            for (int k4 = 0; k4 < 16; k4++) {
                u64t A0,A1,B0,B1,C0,C1,D0,D1,E0,E1;
                lds2(A0, A1, hb + k4*16);
                lds2(B0, B1, hb + 256 + k4*16);
                lds2(C0, C1, hb + 512 + k4*16);
                lds2(D0, D1, hb + 768 + k4*16);
                lds2(E0, E1, hb + 1024 + k4*16);
                int kp = 2 * k4;
                fma2(a0, A0, wp0[kp]);   fma2(a0, B0, wp1[kp]);
                fma2(a1, B0, wp0[kp]);   fma2(a1, C0, wp1[kp]);
                fma2(a2, C0, wp0[kp]);   fma2(a2, D0, wp1[kp]);
                fma2(a3, D0, wp0[kp]);   fma2(a3, E0, wp1[kp]);
                fma2(a0, A1, wp0[kp+1]); fma2(a0, B1, wp1[kp+1]);
                fma2(a1, B1, wp0[kp+1]); fma2(a1, C1, wp1[kp+1]);
                fma2(a2, C1, wp0[kp+1]); fma2(a2, D1, wp1[kp+1]);
                fma2(a3, D1, wp0[kp+1]); fma2(a3, E1, wp1[kp+1]);
            }
            float2 u0 = upk(a0), u1 = upk(a1), u2 = upk(a2), u3 = upk(a3);
            smp[OF_GSM + (m*4+0)*256 + tid] = sig_(u0.x + u0.y);
            smp[OF_GSM + (m*4+1)*256 + tid] = sig_(u1.x + u1.y);
            smp[OF_GSM + (m*4+2)*256 + tid] = sig_(u2.x + u2.y);
            smp[OF_GSM + (m*4+3)*256 + tid] = sig_(u3.x + u3.y);
        }
        __syncthreads();

        // ---- phase 2: c2c + cell/hidden update + producer push ----
        {
            int rl0 = rq * 4;
            unsigned cb = sbase + (OF_C + (p << 10)) * 4;
            unsigned a_m1 = (rl0 == 0) ? (sbase + (OF_CS + p * 64) * 4)
                                       : (cb + (rl0 - 1) * 256);
            unsigned a_0 = cb + rl0 * 256;
            unsigned wcb0 = sbase + OF_WCS * 4 + j * 8;
            unsigned wcb1 = wcb0 + 4096 * 4;
            u64t ac0 = pk(bcj, 0.f), ac1 = ac0, ac2 = ac0, ac3 = ac0;
#pragma unroll
            for (int k4 = 0; k4 < 16; k4++) {
                u64t m0,m1, r00,r01, r10,r11, r20,r21, r30,r31;
                lds2(m0,  m1,  a_m1 + k4*16);
                lds2(r00, r01, a_0 + k4*16);
                lds2(r10, r11, a_0 + 256 + k4*16);
                lds2(r20, r21, a_0 + 512 + k4*16);
                lds2(r30, r31, a_0 + 768 + k4*16);
                int kp = 2 * k4;
                u64t w00 = lds1(wcb0 + kp*512);
                u64t w01 = lds1(wcb0 + kp*512 + 512);
                u64t w10 = lds1(wcb1 + kp*512);
                u64t w11 = lds1(wcb1 + kp*512 + 512);
                fma2(ac0, m0,  w00); fma2(ac0, r00, w10);
                fma2(ac1, r00, w00); fma2(ac1, r10, w10);
                fma2(ac2, r10, w00); fma2(ac2, r20, w10);
                fma2(ac3, r20, w00); fma2(ac3, r30, w10);
                fma2(ac0, m1,  w01); fma2(ac0, r01, w11);
                fma2(ac1, r01, w01); fma2(ac1, r11, w11);
                fma2(ac2, r11, w01); fma2(ac2, r21, w11);
                fma2(ac3, r21, w01); fma2(ac3, r31, w11);
            }
            float2 f0 = upk(ac0), f1 = upk(ac1), f2 = upk(ac2), f3 = upk(ac3);
            float accs[4] = {f0.x + f0.y, f1.x + f1.y, f2.x + f2.y, f3.x + f3.y};
            unsigned hpoff = np * 1280 * 4;
#pragma unroll
            for (int i = 0; i < 4; i++) {
                int rl = rl0 + i;
                int r = r0 + rl;
                int oo = (i << 6) | j;
                float ig = smp[OF_GSM + (0  + rq)*256 + oo];
                float gg = smp[OF_GSM + (4  + rq)*256 + oo];
                float fg = smp[OF_GSM + (8  + rq)*256 + oo];
                float og = smp[OF_GSM + (12 + rq)*256 + oo];
                float cv = fg * accs[i] + ig * gg;
                float hv = og * tanh_(cv);
                smp[OF_C + (np << 10) + rl * 64 + j] = cv;
                if (htg[i][0]) stsc(htg[i][0] + hpoff, hv);
                if (htg[i][1]) stsc(htg[i][1] + hpoff, hv);
                if (i == 3 && ctg) stsc(ctg + np * 256, cv);
                int w = t - r;
                if ((unsigned)w < 64u)
                    g_hbuf[((((b << 6) | r) << 6 | w) << 6) | j] = hv;
            }
        }
    }

    // exit-race fix: all in-flight st.shared::cluster must land before any
    // CTA in the cluster retires.
    CLUSTER_SYNC();
}

// ---------------------------------------------------------------------------
// up: out[b][oc][r][w] = b_up[oc] + sum_j g_hbuf[b][r][w][j] * w_up[oc][j]
// ---------------------------------------------------------------------------
#define UP_SMEM_BYTES ((4096 + 128 * 65) * 4)

__global__ __launch_bounds__(256) void up_kernel(const float* __restrict__ w_up,
                                                 const float* __restrict__ b_up,
                                                 float* __restrict__ out) {
    extern __shared__ float us[];
    float* hsm = us;
    float* osm = us + 4096;
    unsigned hbase = smem_u32(us);
    int b = blockIdx.x >> 6, r = blockIdx.x & 63;
    int tid = threadIdx.x;
    const float* src = g_hbuf + (((b << 6) | r) << 12);
    for (int i = tid; i < 4096; i += 256) hsm[i] = src[i];
    __syncthreads();

    int oc = tid & 127, wh = tid >> 7;
    u64t uu[32];
    const float4* pu = (const float4*)(w_up + (oc << 6));
#pragma unroll
    for (int k4 = 0; k4 < 16; k4++) {
        float4 v = pu[k4];
        uu[2*k4]     = pk(v.x, v.y);
        uu[2*k4 + 1] = pk(v.z, v.w);
    }
    float bu = b_up[oc];
    for (int w = (wh << 5); w < (wh << 5) + 32; w++) {
        u64t a = pk(bu, 0.f);
        unsigned hr = hbase + (w << 8);
#pragma unroll
        for (int k4 = 0; k4 < 16; k4++) {
            u64t x0, x1;
            lds2(x0, x1, hr + k4*16);
            fma2(a, x0, uu[2*k4]);
            fma2(a, x1, uu[2*k4 + 1]);
        }
        float2 f = upk(a);
        osm[oc * 65 + w] = f.x + f.y;
    }
    __syncthreads();

    float* ob = out + (((b << 7) << 6 | r) << 6);
    for (int i = tid; i < 8192; i += 256) {
        int oc2 = i >> 6, w = i & 63;
        ob[(oc2 << 12) | w] = osm[oc2 * 65 + w];
    }
}

extern "C" void kernel_launch(void* const* d_in, const int* in_sizes, int n_in,
                              void* d_out, int out_size) {
    const float* inputs = (const float*)d_in[0];
    const float* w_i2s  = (const float*)d_in[1];
    const float* b_i2s  = (const float*)d_in[2];
    const float* w_s2s  = (const float*)d_in[3];
    const float* b_s2s  = (const float*)d_in[4];
    const float* w_c2c  = (const float*)d_in[5];
    const float* b_c2c  = (const float*)d_in[6];
    const float* w_up   = (const float*)d_in[7];
    const float* b_up   = (const float*)d_in[8];
    float* out = (float*)d_out;

    cudaFuncSetAttribute(scan_kernel, cudaFuncAttributeMaxDynamicSharedMemorySize, SCAN_SMEM_BYTES);
    cudaFuncSetAttribute(up_kernel, cudaFuncAttributeMaxDynamicSharedMemorySize, UP_SMEM_BYTES);

    i2s_kernel<<<2048, 256>>>(inputs, w_i2s, b_i2s);
    scan_kernel<<<128, 256, SCAN_SMEM_BYTES>>>(w_s2s, b_s2s, w_c2c, b_c2c, b_i2s);
    up_kernel<<<2048, 256, UP_SMEM_BYTES>>>(w_up, b_up, out);
}

// round 8
// speedup vs baseline: 2.3267x; 1.0322x over previous
#include <cuda_runtime.h>

#define BB 32
#define NWD 127

__device__ float g_i2s[BB * 64 * 64 * 256];  // [b][r][w][o] (includes b_i2s)
__device__ float g_hbuf[BB * 64 * 64 * 64];  // [b][r][w][j]

typedef unsigned long long u64t;

__device__ __forceinline__ float sig_(float x) { return 1.0f / (1.0f + __expf(-x)); }
__device__ __forceinline__ float tanh_(float x) {
    float e = __expf(-2.0f * x);
    return __fdividef(1.0f - e, 1.0f + e);
}
__device__ __forceinline__ u64t pk(float lo, float hi) {
    u64t r; asm("mov.b64 %0, {%1,%2};" : "=l"(r) : "f"(lo), "f"(hi)); return r;
}
__device__ __forceinline__ float2 upk(u64t v) {
    float2 r; asm("mov.b64 {%0,%1}, %2;" : "=f"(r.x), "=f"(r.y) : "l"(v)); return r;
}
__device__ __forceinline__ void fma2(u64t& d, u64t a, u64t b) {
    asm("fma.rn.f32x2 %0, %1, %2, %0;" : "+l"(d) : "l"(a), "l"(b));
}
__device__ __forceinline__ void lds2(u64t& a, u64t& b, unsigned addr) {
    asm volatile("ld.shared.v2.u64 {%0,%1}, [%2];" : "=l"(a), "=l"(b) : "r"(addr));
}
__device__ __forceinline__ unsigned smem_u32(const void* p) {
    return (unsigned)__cvta_generic_to_shared(p);
}
__device__ __forceinline__ unsigned mapa_rank(unsigned addr, int rank) {
    unsigned r;
    asm("mapa.shared::cluster.u32 %0, %1, %2;" : "=r"(r) : "r"(addr), "r"(rank));
    return r;
}
__device__ __forceinline__ void stsc(unsigned addr, float v) {
    asm volatile("st.shared::cluster.f32 [%0], %1;" :: "r"(addr), "f"(v) : "memory");
}
#define CLUSTER_SYNC() do { \
    asm volatile("barrier.cluster.arrive.aligned;" ::: "memory"); \
    asm volatile("barrier.cluster.wait.aligned;" ::: "memory"); \
} while (0)

// ---------------------------------------------------------------------------
// i2s: g_i2s[b][r][w][o] = b_i2s[o] + sum_c inputs[b][c][r][w] * w_i2s[o][c]
// f32x2 lanes = (w, w+1): x pairs straight from [k][w] smem, scalar weights.
// ---------------------------------------------------------------------------
__global__ __launch_bounds__(256, 2) void i2s_kernel(const float* __restrict__ inputs,
                                                     const float* __restrict__ w_i2s,
                                                     const float* __restrict__ b_i2s) {
    __shared__ float xs[64 * 64];  // [k][w]
    int b = blockIdx.x >> 6, r = blockIdx.x & 63;
    int tid = threadIdx.x;
    for (int i = tid; i < 4096; i += 256) {
        int c = i >> 6, w = i & 63;
        xs[(c << 6) | w] = inputs[((((b << 6) | c) << 6 | r) << 6) | w];
    }
    __syncthreads();

    int o = tid;
    float wk[64];
    {
        const float4* pw = (const float4*)(w_i2s + (o << 6));
#pragma unroll
        for (int k4 = 0; k4 < 16; k4++) {
            float4 v = pw[k4];
            wk[4*k4] = v.x; wk[4*k4+1] = v.y; wk[4*k4+2] = v.z; wk[4*k4+3] = v.w;
        }
    }
    float bu = b_i2s[o];
    u64t binit = pk(bu, bu);
    float* ob = g_i2s + ((((b << 6) | r) << 6) << 8);
    unsigned xb0 = smem_u32(xs);

#pragma unroll 1
    for (int g = 0; g < 4; g++) {
        int w0 = g << 4;
        unsigned xb = xb0 + w0 * 4;
        u64t a0 = binit, a1 = binit, a2 = binit, a3 = binit;
        u64t a4 = binit, a5 = binit, a6 = binit, a7 = binit;
#pragma unroll
        for (int k = 0; k < 64; k++) {
            u64t x0, x1, x2, x3, x4, x5, x6, x7;
            lds2(x0, x1, xb + k * 256);
            lds2(x2, x3, xb + k * 256 + 16);
            lds2(x4, x5, xb + k * 256 + 32);
            lds2(x6, x7, xb + k * 256 + 48);
            u64t wd = pk(wk[k], wk[k]);
            fma2(a0, x0, wd); fma2(a1, x1, wd);
            fma2(a2, x2, wd); fma2(a3, x3, wd);
            fma2(a4, x4, wd); fma2(a5, x5, wd);
            fma2(a6, x6, wd); fma2(a7, x7, wd);
        }
        float2 f;
        f = upk(a0); ob[((w0+0)<<8)|o] = f.x;  ob[((w0+1)<<8)|o] = f.y;
        f = upk(a1); ob[((w0+2)<<8)|o] = f.x;  ob[((w0+3)<<8)|o] = f.y;
        f = upk(a2); ob[((w0+4)<<8)|o] = f.x;  ob[((w0+5)<<8)|o] = f.y;
        f = upk(a3); ob[((w0+6)<<8)|o] = f.x;  ob[((w0+7)<<8)|o] = f.y;
        f = upk(a4); ob[((w0+8)<<8)|o] = f.x;  ob[((w0+9)<<8)|o] = f.y;
        f = upk(a5); ob[((w0+10)<<8)|o] = f.x; ob[((w0+11)<<8)|o] = f.y;
        f = upk(a6); ob[((w0+12)<<8)|o] = f.x; ob[((w0+13)<<8)|o] = f.y;
        f = upk(a7); ob[((w0+14)<<8)|o] = f.x; ob[((w0+15)<<8)|o] = f.y;
    }
}

// ---------------------------------------------------------------------------
// persistent diagonal scan: 128 CTAs x 512 threads, cluster of 4 = one batch.
// smem (float offsets):
//   c_st   @ 0      (2 x 1024)
//   hstage @ 2048   (2 x 1280)
//   cstage @ 4608   (2 x 64)
//   gsm    @ 4736   (4096)    [16][256]
//   wc     @ 8832   (8192)    u64 pair-block: byte addr = kp*1024 + j*16 + s*8
//   ws     @ 17024  (32768)   u64 pair-block: byte addr = kp*4096 + o*16 + s*8
// ---------------------------------------------------------------------------
#define OF_C    0
#define OF_HS   2048
#define OF_CS   4608
#define OF_GSM  4736
#define OF_WC   8832
#define OF_WS   17024
#define SCAN_SMEM_BYTES (49792 * 4)

__global__ void __cluster_dims__(4, 1, 1) __launch_bounds__(512, 1)
scan_kernel(const float* __restrict__ w_s2s,
            const float* __restrict__ b_s2s,
            const float* __restrict__ w_c2c,
            const float* __restrict__ b_c2c,
            const float* __restrict__ b_i2s) {
    extern __shared__ float smp[];
    unsigned sbase = smem_u32(smp);

    int b = blockIdx.x >> 2, rg = blockIdx.x & 3;
    int r0 = rg << 4, q0 = rg << 2;
    int tid = threadIdx.x;
    int o = tid & 255, half = tid >> 8;   // phase-1 mapping
    int j = tid & 63, rq = tid >> 6;      // phase-2 mapping (rq 0..7, 2 rows each)

    // ws fill: float idx = kp*1024 + o2*4 + s*2 + e  -> w_s2s[o2][2kp+e][s]
    for (int i = tid; i < 32768; i += 512) {
        int kp = i >> 10, rr = i & 1023, o2 = rr >> 2, s = (rr >> 1) & 1, e = rr & 1;
        smp[OF_WS + i] = w_s2s[o2 * 128 + (2 * kp + e) * 2 + s];
    }
    // wc fill: float idx = kp*256 + j2*4 + s*2 + e  -> w_c2c[j2][2kp+e][s]
    for (int i = tid; i < 8192; i += 512) {
        int kp = i >> 8, rr = i & 255, j2 = rr >> 2, s = (rr >> 1) & 1, e = rr & 1;
        smp[OF_WC + i] = w_c2c[(j2 * 64 + 2 * kp + e) * 2 + s];
    }
    for (int i = tid; i < 1024; i += 512) smp[OF_C + i] = 0.f;
    for (int i = tid; i < 2560; i += 512) smp[OF_HS + i] = 0.f;
    if (tid < 128) smp[OF_CS + tid] = 0.f;

    float bs = b_s2s[o], bi = b_i2s[o];
    float bcj = b_c2c[j];

    // push targets for rows r = r0 + 2*rq + i (i = 0,1)
    unsigned htg[2][2];
    unsigned ctg = 0;
#pragma unroll
    for (int i = 0; i < 2; i++) {
        int r = r0 + rq * 2 + i;
        htg[i][0] = 0; htg[i][1] = 0;
        int n = 0;
#pragma unroll
        for (int rg2 = 0; rg2 < 4; rg2++) {
            int v = r + 1 - 4 * rg2;
            if (v >= 0) {
                int mm = v >> 4, ii = v & 15;
                if (mm < 4 && ii < 5)
                    htg[i][n++] = mapa_rank(sbase + OF_HS * 4, rg2)
                                  + ((mm * 5 + ii) * 64 + j) * 4;
            }
        }
    }
    if (rq == 7 && rg < 3) ctg = mapa_rank(sbase + OF_CS * 4, rg + 1) + j * 4;

    unsigned wsb = sbase + OF_WS * 4 + o * 16;
    unsigned wcb = sbase + OF_WC * 4 + j * 16;   // FIX: was j*8 (misaligned + wrong data)

    for (int t = 0; t < NWD; t++) {
        int p = t & 1, np = 1 - p;

        // prefetch i2s for this thread's 2 bands
        float xi[8];
#pragma unroll
        for (int ml = 0; ml < 2; ml++) {
            int m = half * 2 + ml;
#pragma unroll
            for (int i = 0; i < 4; i++) {
                int row = q0 + 16 * m + i;
                int w = t - row;
                xi[ml*4+i] = ((unsigned)w < 64u)
                    ? g_i2s[((((b << 6) | row) << 6 | w) << 8) | o] : bi;
            }
        }

        CLUSTER_SYNC();  // pushes from step t-1 visible; stage[p] ready

        // ---- phase 1: bands m = 2*half, 2*half+1 ----
        {
            unsigned hb0 = sbase + (OF_HS + p * 1280 + (half * 2) * 320) * 4;
            unsigned hb1 = hb0 + 1280;
            u64t a0 = pk(bs + xi[0], 0.f), a1 = pk(bs + xi[1], 0.f);
            u64t a2 = pk(bs + xi[2], 0.f), a3 = pk(bs + xi[3], 0.f);
            u64t c0 = pk(bs + xi[4], 0.f), c1 = pk(bs + xi[5], 0.f);
            u64t c2 = pk(bs + xi[6], 0.f), c3 = pk(bs + xi[7], 0.f);
#pragma unroll
            for (int k4 = 0; k4 < 16; k4++) {
                u64t w0A, w1A, w0B, w1B;
                lds2(w0A, w1A, wsb + (2*k4) * 4096);
                lds2(w0B, w1B, wsb + (2*k4+1) * 4096);
                {
                    u64t A0,A1,B0,B1,C0,C1,D0,D1,E0,E1;
                    lds2(A0, A1, hb0 + k4*16);
                    lds2(B0, B1, hb0 + 256 + k4*16);
                    lds2(C0, C1, hb0 + 512 + k4*16);
                    lds2(D0, D1, hb0 + 768 + k4*16);
                    lds2(E0, E1, hb0 + 1024 + k4*16);
                    fma2(a0, A0, w0A); fma2(a0, A1, w0B); fma2(a0, B0, w1A); fma2(a0, B1, w1B);
                    fma2(a1, B0, w0A); fma2(a1, B1, w0B); fma2(a1, C0, w1A); fma2(a1, C1, w1B);
                    fma2(a2, C0, w0A); fma2(a2, C1, w0B); fma2(a2, D0, w1A); fma2(a2, D1, w1B);
                    fma2(a3, D0, w0A); fma2(a3, D1, w0B); fma2(a3, E0, w1A); fma2(a3, E1, w1B);
                }
                {
                    u64t A0,A1,B0,B1,C0,C1,D0,D1,E0,E1;
                    lds2(A0, A1, hb1 + k4*16);
                    lds2(B0, B1, hb1 + 256 + k4*16);
                    lds2(C0, C1, hb1 + 512 + k4*16);
                    lds2(D0, D1, hb1 + 768 + k4*16);
                    lds2(E0, E1, hb1 + 1024 + k4*16);
                    fma2(c0, A0, w0A); fma2(c0, A1, w0B); fma2(c0, B0, w1A); fma2(c0, B1, w1B);
                    fma2(c1, B0, w0A); fma2(c1, B1, w0B); fma2(c1, C0, w1A); fma2(c1, C1, w1B);
                    fma2(c2, C0, w0A); fma2(c2, C1, w0B); fma2(c2, D0, w1A); fma2(c2, D1, w1B);
                    fma2(c3, D0, w0A); fma2(c3, D1, w0B); fma2(c3, E0, w1A); fma2(c3, E1, w1B);
                }
            }
            int m0 = half * 2, m1 = m0 + 1;
            float2 u;
            u = upk(a0); smp[OF_GSM + (m0*4+0)*256 + o] = sig_(u.x + u.y);
            u = upk(a1); smp[OF_GSM + (m0*4+1)*256 + o] = sig_(u.x + u.y);
            u = upk(a2); smp[OF_GSM + (m0*4+2)*256 + o] = sig_(u.x + u.y);
            u = upk(a3); smp[OF_GSM + (m0*4+3)*256 + o] = sig_(u.x + u.y);
            u = upk(c0); smp[OF_GSM + (m1*4+0)*256 + o] = sig_(u.x + u.y);
            u = upk(c1); smp[OF_GSM + (m1*4+1)*256 + o] = sig_(u.x + u.y);
            u = upk(c2); smp[OF_GSM + (m1*4+2)*256 + o] = sig_(u.x + u.y);
            u = upk(c3); smp[OF_GSM + (m1*4+3)*256 + o] = sig_(u.x + u.y);
        }
        __syncthreads();

        // ---- phase 2: rows rl = 2*rq, 2*rq+1 ----
        {
            int rl0 = rq * 2;
            unsigned cb = sbase + (OF_C + (p << 10)) * 4;
            unsigned a_m1 = (rl0 == 0) ? (sbase + (OF_CS + p * 64) * 4)
                                       : (cb + (rl0 - 1) * 256);
            unsigned a_0 = cb + rl0 * 256;
            unsigned a_1 = a_0 + 256;
            u64t ac0 = pk(bcj, 0.f), ac1 = ac0;
#pragma unroll
            for (int k4 = 0; k4 < 16; k4++) {
                u64t w0A, w1A, w0B, w1B;
                lds2(w0A, w1A, wcb + (2*k4) * 1024);
                lds2(w0B, w1B, wcb + (2*k4+1) * 1024);
                u64t m0,m1, r00,r01, r10,r11;
                lds2(m0,  m1,  a_m1 + k4*16);
                lds2(r00, r01, a_0 + k4*16);
                lds2(r10, r11, a_1 + k4*16);
                fma2(ac0, m0,  w0A); fma2(ac0, m1,  w0B);
                fma2(ac0, r00, w1A); fma2(ac0, r01, w1B);
                fma2(ac1, r00, w0A); fma2(ac1, r01, w0B);
                fma2(ac1, r10, w1A); fma2(ac1, r11, w1B);
            }
            float2 f0 = upk(ac0), f1 = upk(ac1);
            float accs[2] = {f0.x + f0.y, f1.x + f1.y};
            unsigned hpoff = np * 1280 * 4;
#pragma unroll
            for (int i = 0; i < 2; i++) {
                int rl = rl0 + i;
                int r = r0 + rl;
                int a = rl >> 2;
                int oo = ((rl & 3) << 6) | j;
                float ig = smp[OF_GSM + (0  + a)*256 + oo];
                float gg = smp[OF_GSM + (4  + a)*256 + oo];
                float fg = smp[OF_GSM + (8  + a)*256 + oo];
                float og = smp[OF_GSM + (12 + a)*256 + oo];
                float cv = fg * accs[i] + ig * gg;
                float hv = og * tanh_(cv);
                smp[OF_C + (np << 10) + rl * 64 + j] = cv;
                if (htg[i][0]) stsc(htg[i][0] + hpoff, hv);
                if (htg[i][1]) stsc(htg[i][1] + hpoff, hv);
                if (i == 1 && ctg) stsc(ctg + np * 256, cv);
                int w = t - r;
                if ((unsigned)w < 64u)
                    g_hbuf[((((b << 6) | r) << 6 | w) << 6) | j] = hv;
            }
        }
    }

    CLUSTER_SYNC();  // exit-race guard for in-flight cluster stores
}

// ---------------------------------------------------------------------------
// up: out[b][oc][r][w] = b_up[oc] + sum_j g_hbuf[b][r][w][j] * w_up[oc][j]
// ---------------------------------------------------------------------------
#define UP_SMEM_BYTES ((4096 + 128 * 65) * 4)

__global__ __launch_bounds__(256) void up_kernel(const float* __restrict__ w_up,
                                                 const float* __restrict__ b_up,
                                                 float* __restrict__ out) {
    extern __shared__ float us[];
    float* hsm = us;
    float* osm = us + 4096;
    unsigned hbase = smem_u32(us);
    int b = blockIdx.x >> 6, r = blockIdx.x & 63;
    int tid = threadIdx.x;
    const float* src = g_hbuf + (((b << 6) | r) << 12);
    for (int i = tid; i < 4096; i += 256) hsm[i] = src[i];
    __syncthreads();

    int oc = tid & 127, wh = tid >> 7;
    u64t uu[32];
    const float4* pu = (const float4*)(w_up + (oc << 6));
#pragma unroll
    for (int k4 = 0; k4 < 16; k4++) {
        float4 v = pu[k4];
        uu[2*k4]     = pk(v.x, v.y);
        uu[2*k4 + 1] = pk(v.z, v.w);
    }
    float bu = b_up[oc];
    for (int w = (wh << 5); w < (wh << 5) + 32; w++) {
        u64t a = pk(bu, 0.f);
        unsigned hr = hbase + (w << 8);
#pragma unroll
        for (int k4 = 0; k4 < 16; k4++) {
            u64t x0, x1;
            lds2(x0, x1, hr + k4*16);
            fma2(a, x0, uu[2*k4]);
            fma2(a, x1, uu[2*k4 + 1]);
        }
        float2 f = upk(a);
        osm[oc * 65 + w] = f.x + f.y;
    }
    __syncthreads();

    float* ob = out + (((b << 7) << 6 | r) << 6);
    for (int i = tid; i < 8192; i += 256) {
        int oc2 = i >> 6, w = i & 63;
        ob[(oc2 << 12) | w] = osm[oc2 * 65 + w];
    }
}

extern "C" void kernel_launch(void* const* d_in, const int* in_sizes, int n_in,
                              void* d_out, int out_size) {
    const float* inputs = (const float*)d_in[0];
    const float* w_i2s  = (const float*)d_in[1];
    const float* b_i2s  = (const float*)d_in[2];
    const float* w_s2s  = (const float*)d_in[3];
    const float* b_s2s  = (const float*)d_in[4];
    const float* w_c2c  = (const float*)d_in[5];
    const float* b_c2c  = (const float*)d_in[6];
    const float* w_up   = (const float*)d_in[7];
    const float* b_up   = (const float*)d_in[8];
    float* out = (float*)d_out;

    cudaFuncSetAttribute(scan_kernel, cudaFuncAttributeMaxDynamicSharedMemorySize, SCAN_SMEM_BYTES);
    cudaFuncSetAttribute(up_kernel, cudaFuncAttributeMaxDynamicSharedMemorySize, UP_SMEM_BYTES);

    i2s_kernel<<<2048, 256>>>(inputs, w_i2s, b_i2s);
    scan_kernel<<<128, 512, SCAN_SMEM_BYTES>>>(w_s2s, b_s2s, w_c2c, b_c2c, b_i2s);
    up_kernel<<<2048, 256, UP_SMEM_BYTES>>>(w_up, b_up, out);
}

// round 9
// speedup vs baseline: 2.5594x; 1.1001x over previous
#include <cuda_runtime.h>

#define BB 32
#define NWD 127

__device__ float g_i2s[BB * 64 * 64 * 256];  // [b][r][w][o] (includes b_i2s)
__device__ float g_hbuf[BB * 64 * 64 * 64];  // [b][r][w][j]

typedef unsigned long long u64t;

__device__ __forceinline__ float sig_(float x) { return 1.0f / (1.0f + __expf(-x)); }
__device__ __forceinline__ float tanh_(float x) {
    float e = __expf(-2.0f * x);
    return __fdividef(1.0f - e, 1.0f + e);
}
__device__ __forceinline__ u64t pk(float lo, float hi) {
    u64t r; asm("mov.b64 %0, {%1,%2};" : "=l"(r) : "f"(lo), "f"(hi)); return r;
}
__device__ __forceinline__ float2 upk(u64t v) {
    float2 r; asm("mov.b64 {%0,%1}, %2;" : "=f"(r.x), "=f"(r.y) : "l"(v)); return r;
}
__device__ __forceinline__ void fma2(u64t& d, u64t a, u64t b) {
    asm("fma.rn.f32x2 %0, %1, %2, %0;" : "+l"(d) : "l"(a), "l"(b));
}
__device__ __forceinline__ void lds2(u64t& a, u64t& b, unsigned addr) {
    asm volatile("ld.shared.v2.u64 {%0,%1}, [%2];" : "=l"(a), "=l"(b) : "r"(addr));
}
__device__ __forceinline__ unsigned smem_u32(const void* p) {
    return (unsigned)__cvta_generic_to_shared(p);
}
__device__ __forceinline__ unsigned mapa_rank(unsigned addr, int rank) {
    unsigned r;
    asm("mapa.shared::cluster.u32 %0, %1, %2;" : "=r"(r) : "r"(addr), "r"(rank));
    return r;
}
__device__ __forceinline__ void stsc(unsigned addr, float v) {
    asm volatile("st.shared::cluster.f32 [%0], %1;" :: "r"(addr), "f"(v) : "memory");
}
#define CLUSTER_SYNC() do { \
    asm volatile("barrier.cluster.arrive.aligned;" ::: "memory"); \
    asm volatile("barrier.cluster.wait.aligned;" ::: "memory"); \
} while (0)

// ---------------------------------------------------------------------------
// i2s (unchanged from R8): g_i2s[b][r][w][o] = b_i2s[o] + sum_c x*w
// ---------------------------------------------------------------------------
__global__ __launch_bounds__(256, 2) void i2s_kernel(const float* __restrict__ inputs,
                                                     const float* __restrict__ w_i2s,
                                                     const float* __restrict__ b_i2s) {
    __shared__ float xs[64 * 64];  // [k][w]
    int b = blockIdx.x >> 6, r = blockIdx.x & 63;
    int tid = threadIdx.x;
    for (int i = tid; i < 4096; i += 256) {
        int c = i >> 6, w = i & 63;
        xs[(c << 6) | w] = inputs[((((b << 6) | c) << 6 | r) << 6) | w];
    }
    __syncthreads();

    int o = tid;
    float wk[64];
    {
        const float4* pw = (const float4*)(w_i2s + (o << 6));
#pragma unroll
        for (int k4 = 0; k4 < 16; k4++) {
            float4 v = pw[k4];
            wk[4*k4] = v.x; wk[4*k4+1] = v.y; wk[4*k4+2] = v.z; wk[4*k4+3] = v.w;
        }
    }
    float bu = b_i2s[o];
    u64t binit = pk(bu, bu);
    float* ob = g_i2s + ((((b << 6) | r) << 6) << 8);
    unsigned xb0 = smem_u32(xs);

#pragma unroll 1
    for (int g = 0; g < 4; g++) {
        int w0 = g << 4;
        unsigned xb = xb0 + w0 * 4;
        u64t a0 = binit, a1 = binit, a2 = binit, a3 = binit;
        u64t a4 = binit, a5 = binit, a6 = binit, a7 = binit;
#pragma unroll
        for (int k = 0; k < 64; k++) {
            u64t x0, x1, x2, x3, x4, x5, x6, x7;
            lds2(x0, x1, xb + k * 256);
            lds2(x2, x3, xb + k * 256 + 16);
            lds2(x4, x5, xb + k * 256 + 32);
            lds2(x6, x7, xb + k * 256 + 48);
            u64t wd = pk(wk[k], wk[k]);
            fma2(a0, x0, wd); fma2(a1, x1, wd);
            fma2(a2, x2, wd); fma2(a3, x3, wd);
            fma2(a4, x4, wd); fma2(a5, x5, wd);
            fma2(a6, x6, wd); fma2(a7, x7, wd);
        }
        float2 f;
        f = upk(a0); ob[((w0+0)<<8)|o] = f.x;  ob[((w0+1)<<8)|o] = f.y;
        f = upk(a1); ob[((w0+2)<<8)|o] = f.x;  ob[((w0+3)<<8)|o] = f.y;
        f = upk(a2); ob[((w0+4)<<8)|o] = f.x;  ob[((w0+5)<<8)|o] = f.y;
        f = upk(a3); ob[((w0+6)<<8)|o] = f.x;  ob[((w0+7)<<8)|o] = f.y;
        f = upk(a4); ob[((w0+8)<<8)|o] = f.x;  ob[((w0+9)<<8)|o] = f.y;
        f = upk(a5); ob[((w0+10)<<8)|o] = f.x; ob[((w0+11)<<8)|o] = f.y;
        f = upk(a6); ob[((w0+12)<<8)|o] = f.x; ob[((w0+13)<<8)|o] = f.y;
        f = upk(a7); ob[((w0+14)<<8)|o] = f.x; ob[((w0+15)<<8)|o] = f.y;
    }
}

// ---------------------------------------------------------------------------
// persistent scan, split-K: 128 CTAs x 512 threads, cluster of 4 = one batch.
// thread = (o in 0..255, kh in 0..1); w_s2s half lives in registers (64 regs).
// partials meet in smem. phase-2 also split-k (weights from smem, 16B loads).
// smem (float offsets):
//   c_st  @ 0     (2 x 1024)
//   hstage@ 2048  (2 x 1280)   [par][band m][ii 0..4][k]
//   cstage@ 4608  (2 x 64)
//   gsm   @ 4736  (4096)       [16][256]
//   P1    @ 8832  (2 x 4096)   [kh][16 gate rows][256]
//   P2    @ 17024 (2 x 1024)   [kh][16 rows][64]
//   wc    @ 19072 (8192)       u64 pair-block: byte = kp*1024 + j*16
// total 27264 floats = 109056 B
// ---------------------------------------------------------------------------
#define OF_C    0
#define OF_HS   2048
#define OF_CS   4608
#define OF_GSM  4736
#define OF_P1   8832
#define OF_P2   17024
#define OF_WC   19072
#define SCAN_SMEM_BYTES (27264 * 4)

__global__ void __cluster_dims__(4, 1, 1) __launch_bounds__(512, 1)
scan_kernel(const float* __restrict__ w_s2s,
            const float* __restrict__ b_s2s,
            const float* __restrict__ w_c2c,
            const float* __restrict__ b_c2c,
            const float* __restrict__ b_i2s) {
    extern __shared__ float smp[];
    unsigned sbase = smem_u32(smp);

    int b = blockIdx.x >> 2, rg = blockIdx.x & 3;
    int r0 = rg << 4, q0 = rg << 2;
    int tid = threadIdx.x;
    int o = tid & 255, kh = tid >> 8;       // phase-1: output o, k-half kh
    int j = tid & 63, g6 = tid >> 6;        // phase-2: j, group g6 (quad = g6&3, k-half = g6>>2 == kh)
    int quad = g6 & 3;
    int rq = g6;                            // combine-2: rows 2rq, 2rq+1

    // persistent s2s weights for this k-half (32 k, packed pairs) = 64 regs
    u64t wp0[16], wp1[16];
    {
        const float4* wp = (const float4*)(w_s2s + o * 128 + kh * 64);
#pragma unroll
        for (int k2 = 0; k2 < 16; k2++) {
            float4 v = wp[k2];
            wp0[k2] = pk(v.x, v.z);
            wp1[k2] = pk(v.y, v.w);
        }
    }
    float bs = b_s2s[o], bi = b_i2s[o];
    float bcj = b_c2c[j];

    // wc fill: float idx = kp*256 + j2*4 + s*2 + e  -> w_c2c[j2][2kp+e][s]
    for (int i = tid; i < 8192; i += 512) {
        int kp = i >> 8, rr = i & 255, j2 = rr >> 2, s = (rr >> 1) & 1, e = rr & 1;
        smp[OF_WC + i] = w_c2c[(j2 * 64 + 2 * kp + e) * 2 + s];
    }
    for (int i = tid; i < 1024; i += 512) smp[OF_C + i] = 0.f;
    for (int i = tid; i < 2560; i += 512) smp[OF_HS + i] = 0.f;
    if (tid < 128) smp[OF_CS + tid] = 0.f;

    // push targets for rows r = r0 + 2*rq + i (i = 0,1)
    unsigned htg[2][2];
    unsigned ctg = 0;
#pragma unroll
    for (int i = 0; i < 2; i++) {
        int r = r0 + rq * 2 + i;
        htg[i][0] = 0; htg[i][1] = 0;
        int n = 0;
#pragma unroll
        for (int rg2 = 0; rg2 < 4; rg2++) {
            int v = r + 1 - 4 * rg2;
            if (v >= 0) {
                int mm = v >> 4, ii = v & 15;
                if (mm < 4 && ii < 5)
                    htg[i][n++] = mapa_rank(sbase + OF_HS * 4, rg2)
                                  + ((mm * 5 + ii) * 64 + j) * 4;
            }
        }
    }
    if (rq == 7 && rg < 3) ctg = mapa_rank(sbase + OF_CS * 4, rg + 1) + j * 4;

    unsigned wq = sbase + OF_WC * 4 + j * 16;  // + kp*1024

    for (int t = 0; t < NWD; t++) {
        int p = t & 1, np = 1 - p;

        // prefetch i2s: this thread combines gate rows lr = kh*8 .. kh*8+7
        float xi[8];
#pragma unroll
        for (int ii = 0; ii < 8; ii++) {
            int lr = kh * 8 + ii;
            int row = q0 + 16 * (lr >> 2) + (lr & 3);
            int w = t - row;
            xi[ii] = ((unsigned)w < 64u)
                ? g_i2s[((((b << 6) | row) << 6 | w) << 8) | o] : bi;
        }

        CLUSTER_SYNC();  // pushes from step t-1 visible; stage[p], c_st[p] ready

        // ---- phase 1 partials: 16 gate rows over this k-half ----
        {
            unsigned hbB = sbase + (OF_HS + p * 1280) * 4 + kh * 128;
#pragma unroll
            for (int m = 0; m < 4; m++) {
                u64t a0 = 0, a1 = 0, a2 = 0, a3 = 0;
                unsigned hb = hbB + m * 1280;
#pragma unroll
                for (int k4 = 0; k4 < 8; k4++) {
                    u64t A0,A1,B0,B1,C0,C1,D0,D1,E0,E1;
                    lds2(A0, A1, hb + k4*16);
                    lds2(B0, B1, hb + 256 + k4*16);
                    lds2(C0, C1, hb + 512 + k4*16);
                    lds2(D0, D1, hb + 768 + k4*16);
                    lds2(E0, E1, hb + 1024 + k4*16);
                    int kp = 2 * k4;
                    fma2(a0, A0, wp0[kp]);   fma2(a0, B0, wp1[kp]);
                    fma2(a1, B0, wp0[kp]);   fma2(a1, C0, wp1[kp]);
                    fma2(a2, C0, wp0[kp]);   fma2(a2, D0, wp1[kp]);
                    fma2(a3, D0, wp0[kp]);   fma2(a3, E0, wp1[kp]);
                    fma2(a0, A1, wp0[kp+1]); fma2(a0, B1, wp1[kp+1]);
                    fma2(a1, B1, wp0[kp+1]); fma2(a1, C1, wp1[kp+1]);
                    fma2(a2, C1, wp0[kp+1]); fma2(a2, D1, wp1[kp+1]);
                    fma2(a3, D1, wp0[kp+1]); fma2(a3, E1, wp1[kp+1]);
                }
                float2 u;
                int base = OF_P1 + kh * 4096 + (m * 4) * 256 + o;
                u = upk(a0); smp[base]       = u.x + u.y;
                u = upk(a1); smp[base + 256] = u.x + u.y;
                u = upk(a2); smp[base + 512] = u.x + u.y;
                u = upk(a3); smp[base + 768] = u.x + u.y;
            }
        }

        // ---- phase 2 partials: quad rows over this k-half ----
        {
            int rl0 = quad * 4;
            unsigned cb = sbase + (OF_C + (p << 10)) * 4;
            unsigned a_m1 = (rl0 == 0) ? (sbase + (OF_CS + p * 64) * 4 + kh * 128)
                                       : (cb + (rl0 - 1) * 256 + kh * 128);
            unsigned a_0 = cb + rl0 * 256 + kh * 128;
            int kpbase = kh * 16;
            u64t ac0 = 0, ac1 = 0, ac2 = 0, ac3 = 0;
#pragma unroll
            for (int k4 = 0; k4 < 8; k4++) {
                u64t w0A, w1A, w0B, w1B;
                lds2(w0A, w1A, wq + (kpbase + 2*k4) * 1024);
                lds2(w0B, w1B, wq + (kpbase + 2*k4 + 1) * 1024);
                u64t m0,m1, r00,r01, r10,r11, r20,r21, r30,r31;
                lds2(m0,  m1,  a_m1 + k4*16);
                lds2(r00, r01, a_0 + k4*16);
                lds2(r10, r11, a_0 + 256 + k4*16);
                lds2(r20, r21, a_0 + 512 + k4*16);
                lds2(r30, r31, a_0 + 768 + k4*16);
                fma2(ac0, m0,  w0A); fma2(ac0, r00, w1A);
                fma2(ac1, r00, w0A); fma2(ac1, r10, w1A);
                fma2(ac2, r10, w0A); fma2(ac2, r20, w1A);
                fma2(ac3, r20, w0A); fma2(ac3, r30, w1A);
                fma2(ac0, m1,  w0B); fma2(ac0, r01, w1B);
                fma2(ac1, r01, w0B); fma2(ac1, r11, w1B);
                fma2(ac2, r11, w0B); fma2(ac2, r21, w1B);
                fma2(ac3, r21, w0B); fma2(ac3, r31, w1B);
            }
            float2 u;
            int base = OF_P2 + kh * 1024 + rl0 * 64 + j;
            u = upk(ac0); smp[base]       = u.x + u.y;
            u = upk(ac1); smp[base + 64]  = u.x + u.y;
            u = upk(ac2); smp[base + 128] = u.x + u.y;
            u = upk(ac3); smp[base + 192] = u.x + u.y;
        }
        __syncthreads();  // P1, P2 visible

        // ---- combine 1: gates for rows lr = kh*8 .. kh*8+7 ----
#pragma unroll
        for (int ii = 0; ii < 8; ii++) {
            int lr = kh * 8 + ii;
            float p0v = smp[OF_P1 + lr * 256 + o];
            float p1v = smp[OF_P1 + 4096 + lr * 256 + o];
            smp[OF_GSM + lr * 256 + o] = sig_(xi[ii] + bs + p0v + p1v);
        }
        __syncthreads();  // gsm visible

        // ---- combine 2: rows 2rq, 2rq+1 -> c,h update + pushes ----
        {
            unsigned hpoff = np * 1280 * 4;
#pragma unroll
            for (int i = 0; i < 2; i++) {
                int rl = rq * 2 + i;
                int r = r0 + rl;
                float acc = bcj + smp[OF_P2 + rl * 64 + j]
                                + smp[OF_P2 + 1024 + rl * 64 + j];
                int a = rl >> 2;
                int oo = ((rl & 3) << 6) | j;
                float ig = smp[OF_GSM + (0  + a)*256 + oo];
                float gg = smp[OF_GSM + (4  + a)*256 + oo];
                float fg = smp[OF_GSM + (8  + a)*256 + oo];
                float og = smp[OF_GSM + (12 + a)*256 + oo];
                float cv = fg * acc + ig * gg;
                float hv = og * tanh_(cv);
                smp[OF_C + (np << 10) + rl * 64 + j] = cv;
                if (htg[i][0]) stsc(htg[i][0] + hpoff, hv);
                if (htg[i][1]) stsc(htg[i][1] + hpoff, hv);
                if (i == 1 && ctg) stsc(ctg + np * 256, cv);
                int w = t - r;
                if ((unsigned)w < 64u)
                    g_hbuf[((((b << 6) | r) << 6 | w) << 6) | j] = hv;
            }
        }
    }

    CLUSTER_SYNC();  // exit-race guard for in-flight cluster stores
}

// ---------------------------------------------------------------------------
// up (unchanged from R8)
// ---------------------------------------------------------------------------
#define UP_SMEM_BYTES ((4096 + 128 * 65) * 4)

__global__ __launch_bounds__(256) void up_kernel(const float* __restrict__ w_up,
                                                 const float* __restrict__ b_up,
                                                 float* __restrict__ out) {
    extern __shared__ float us[];
    float* hsm = us;
    float* osm = us + 4096;
    unsigned hbase = smem_u32(us);
    int b = blockIdx.x >> 6, r = blockIdx.x & 63;
    int tid = threadIdx.x;
    const float* src = g_hbuf + (((b << 6) | r) << 12);
    for (int i = tid; i < 4096; i += 256) hsm[i] = src[i];
    __syncthreads();

    int oc = tid & 127, wh = tid >> 7;
    u64t uu[32];
    const float4* pu = (const float4*)(w_up + (oc << 6));
#pragma unroll
    for (int k4 = 0; k4 < 16; k4++) {
        float4 v = pu[k4];
        uu[2*k4]     = pk(v.x, v.y);
        uu[2*k4 + 1] = pk(v.z, v.w);
    }
    float bu = b_up[oc];
    for (int w = (wh << 5); w < (wh << 5) + 32; w++) {
        u64t a = pk(bu, 0.f);
        unsigned hr = hbase + (w << 8);
#pragma unroll
        for (int k4 = 0; k4 < 16; k4++) {
            u64t x0, x1;
            lds2(x0, x1, hr + k4*16);
            fma2(a, x0, uu[2*k4]);
            fma2(a, x1, uu[2*k4 + 1]);
        }
        float2 f = upk(a);
        osm[oc * 65 + w] = f.x + f.y;
    }
    __syncthreads();

    float* ob = out + (((b << 7) << 6 | r) << 6);
    for (int i = tid; i < 8192; i += 256) {
        int oc2 = i >> 6, w = i & 63;
        ob[(oc2 << 12) | w] = osm[oc2 * 65 + w];
    }
}

extern "C" void kernel_launch(void* const* d_in, const int* in_sizes, int n_in,
                              void* d_out, int out_size) {
    const float* inputs = (const float*)d_in[0];
    const float* w_i2s  = (const float*)d_in[1];
    const float* b_i2s  = (const float*)d_in[2];
    const float* w_s2s  = (const float*)d_in[3];
    const float* b_s2s  = (const float*)d_in[4];
    const float* w_c2c  = (const float*)d_in[5];
    const float* b_c2c  = (const float*)d_in[6];
    const float* w_up   = (const float*)d_in[7];
    const float* b_up   = (const float*)d_in[8];
    float* out = (float*)d_out;

    cudaFuncSetAttribute(scan_kernel, cudaFuncAttributeMaxDynamicSharedMemorySize, SCAN_SMEM_BYTES);
    cudaFuncSetAttribute(up_kernel, cudaFuncAttributeMaxDynamicSharedMemorySize, UP_SMEM_BYTES);

    i2s_kernel<<<2048, 256>>>(inputs, w_i2s, b_i2s);
    scan_kernel<<<128, 512, SCAN_SMEM_BYTES>>>(w_s2s, b_s2s, w_c2c, b_c2c, b_i2s);
    up_kernel<<<2048, 256, UP_SMEM_BYTES>>>(w_up, b_up, out);
}

// round 10
// speedup vs baseline: 2.6783x; 1.0465x over previous
#include <cuda_runtime.h>

#define BB 32
#define NWD 127

__device__ float g_i2s[BB * 64 * 64 * 256];  // [b][r][w][o] (includes b_i2s)
__device__ float g_hbuf[BB * 64 * 64 * 64];  // [b][r][w][j]

typedef unsigned long long u64t;

__device__ __forceinline__ float sig_(float x) { return 1.0f / (1.0f + __expf(-x)); }
__device__ __forceinline__ float tanh_(float x) {
    float e = __expf(-2.0f * x);
    return __fdividef(1.0f - e, 1.0f + e);
}
__device__ __forceinline__ u64t pk(float lo, float hi) {
    u64t r; asm("mov.b64 %0, {%1,%2};" : "=l"(r) : "f"(lo), "f"(hi)); return r;
}
__device__ __forceinline__ float2 upk(u64t v) {
    float2 r; asm("mov.b64 {%0,%1}, %2;" : "=f"(r.x), "=f"(r.y) : "l"(v)); return r;
}
__device__ __forceinline__ void fma2(u64t& d, u64t a, u64t b) {
    asm("fma.rn.f32x2 %0, %1, %2, %0;" : "+l"(d) : "l"(a), "l"(b));
}
__device__ __forceinline__ void lds2(u64t& a, u64t& b, unsigned addr) {
    asm volatile("ld.shared.v2.u64 {%0,%1}, [%2];" : "=l"(a), "=l"(b) : "r"(addr));
}
__device__ __forceinline__ unsigned smem_u32(const void* p) {
    return (unsigned)__cvta_generic_to_shared(p);
}
__device__ __forceinline__ unsigned mapa_rank(unsigned addr, int rank) {
    unsigned r;
    asm("mapa.shared::cluster.u32 %0, %1, %2;" : "=r"(r) : "r"(addr), "r"(rank));
    return r;
}
__device__ __forceinline__ void stsc(unsigned addr, float v) {
    asm volatile("st.shared::cluster.f32 [%0], %1;" :: "r"(addr), "f"(v) : "memory");
}
#define CLUSTER_SYNC() do { \
    asm volatile("barrier.cluster.arrive.aligned;" ::: "memory"); \
    asm volatile("barrier.cluster.wait.aligned;" ::: "memory"); \
} while (0)

// ---------------------------------------------------------------------------
// i2s: 2 rows per block (weights amortized). grid 1024 = b(32) x rowpair(32).
// ---------------------------------------------------------------------------
__global__ __launch_bounds__(256, 2) void i2s_kernel(const float* __restrict__ inputs,
                                                     const float* __restrict__ w_i2s,
                                                     const float* __restrict__ b_i2s) {
    __shared__ float xs[2 * 4096];  // [rr][k][w]
    int b = blockIdx.x >> 5, rp = blockIdx.x & 31;
    int tid = threadIdx.x;
    for (int i = tid; i < 8192; i += 256) {
        int rr = i >> 12, c = (i >> 6) & 63, w = i & 63;
        xs[i] = inputs[((((b << 6) | c) << 6 | (rp * 2 + rr)) << 6) | w];
    }
    __syncthreads();

    int o = tid;
    float wk[64];
    {
        const float4* pw = (const float4*)(w_i2s + (o << 6));
#pragma unroll
        for (int k4 = 0; k4 < 16; k4++) {
            float4 v = pw[k4];
            wk[4*k4] = v.x; wk[4*k4+1] = v.y; wk[4*k4+2] = v.z; wk[4*k4+3] = v.w;
        }
    }
    float bu = b_i2s[o];
    u64t binit = pk(bu, bu);

#pragma unroll 1
    for (int rr = 0; rr < 2; rr++) {
        float* ob = g_i2s + ((((b << 6) | (rp * 2 + rr)) << 6) << 8);
        unsigned xb0 = smem_u32(xs) + rr * 16384;
#pragma unroll 1
        for (int g = 0; g < 4; g++) {
            int w0 = g << 4;
            unsigned xb = xb0 + w0 * 4;
            u64t a0 = binit, a1 = binit, a2 = binit, a3 = binit;
            u64t a4 = binit, a5 = binit, a6 = binit, a7 = binit;
#pragma unroll
            for (int k = 0; k < 64; k++) {
                u64t x0, x1, x2, x3, x4, x5, x6, x7;
                lds2(x0, x1, xb + k * 256);
                lds2(x2, x3, xb + k * 256 + 16);
                lds2(x4, x5, xb + k * 256 + 32);
                lds2(x6, x7, xb + k * 256 + 48);
                u64t wd = pk(wk[k], wk[k]);
                fma2(a0, x0, wd); fma2(a1, x1, wd);
                fma2(a2, x2, wd); fma2(a3, x3, wd);
                fma2(a4, x4, wd); fma2(a5, x5, wd);
                fma2(a6, x6, wd); fma2(a7, x7, wd);
            }
            float2 f;
            f = upk(a0); ob[((w0+0)<<8)|o] = f.x;  ob[((w0+1)<<8)|o] = f.y;
            f = upk(a1); ob[((w0+2)<<8)|o] = f.x;  ob[((w0+3)<<8)|o] = f.y;
            f = upk(a2); ob[((w0+4)<<8)|o] = f.x;  ob[((w0+5)<<8)|o] = f.y;
            f = upk(a3); ob[((w0+6)<<8)|o] = f.x;  ob[((w0+7)<<8)|o] = f.y;
            f = upk(a4); ob[((w0+8)<<8)|o] = f.x;  ob[((w0+9)<<8)|o] = f.y;
            f = upk(a5); ob[((w0+10)<<8)|o] = f.x; ob[((w0+11)<<8)|o] = f.y;
            f = upk(a6); ob[((w0+12)<<8)|o] = f.x; ob[((w0+13)<<8)|o] = f.y;
            f = upk(a7); ob[((w0+14)<<8)|o] = f.x; ob[((w0+15)<<8)|o] = f.y;
        }
    }
}

// ---------------------------------------------------------------------------
// persistent scan, split-K + fused combine (gsm eliminated, 1 syncthreads/step)
// 128 CTAs x 512 threads, cluster of 4 = one batch.
// smem (float offsets):
//   c_st  @ 0      (2 x 1024)
//   hstage@ 2048   (2 x 1280)
//   cstage@ 4608   (2 x 64)
//   P1    @ 4736   (2 x 4096)  [kh][16 gate rows][256]
//   P2    @ 12928  (2 x 1024)  [kh][16 rows][64]
//   wc    @ 14976  (8192)      u64 pair-block: byte = kp*1024 + j*16
// total 23168 floats = 92672 B
// ---------------------------------------------------------------------------
#define OF_C    0
#define OF_HS   2048
#define OF_CS   4608
#define OF_P1   4736
#define OF_P2   12928
#define OF_WC   14976
#define SCAN_SMEM_BYTES (23168 * 4)

__global__ void __cluster_dims__(4, 1, 1) __launch_bounds__(512, 1)
scan_kernel(const float* __restrict__ w_s2s,
            const float* __restrict__ b_s2s,
            const float* __restrict__ w_c2c,
            const float* __restrict__ b_c2c,
            const float* __restrict__ b_i2s) {
    extern __shared__ float smp[];
    unsigned sbase = smem_u32(smp);

    int b = blockIdx.x >> 2, rg = blockIdx.x & 3;
    int r0 = rg << 4, q0 = rg << 2;
    int tid = threadIdx.x;
    int o = tid & 255, kh = tid >> 8;   // phase-1: output o, k-half kh
    int j = tid & 63, g6 = tid >> 6;    // phase-2: j, group
    int quad = g6 & 3;                  // phase-2 partials: rows quad*4..+3, k-half g6>>2 == kh
    int rq = g6;                        // combine: cells rows 2rq, 2rq+1

    // persistent s2s weights for this k-half (32 k, packed pairs) = 64 regs
    u64t wp0[16], wp1[16];
    {
        const float4* wp = (const float4*)(w_s2s + o * 128 + kh * 64);
#pragma unroll
        for (int k2 = 0; k2 < 16; k2++) {
            float4 v = wp[k2];
            wp0[k2] = pk(v.x, v.z);
            wp1[k2] = pk(v.y, v.w);
        }
    }
    float bcj = b_c2c[j];

    // consumer-side constants (fused combine): cells (2rq+i, j)
    int rlA = 2 * rq, rlB = 2 * rq + 1;
    int aA = rlA >> 2;  // == rlB >> 2
    int ooA = ((rlA & 3) << 6) | j;
    int ooB = ((rlB & 3) << 6) | j;
    float bsA = b_s2s[ooA], bsB = b_s2s[ooB];
    float biA = b_i2s[ooA], biB = b_i2s[ooB];

    // wc fill: float idx = kp*256 + j2*4 + s*2 + e  -> w_c2c[j2][2kp+e][s]
    for (int i = tid; i < 8192; i += 512) {
        int kp = i >> 8, rr = i & 255, j2 = rr >> 2, s = (rr >> 1) & 1, e = rr & 1;
        smp[OF_WC + i] = w_c2c[(j2 * 64 + 2 * kp + e) * 2 + s];
    }
    for (int i = tid; i < 1024; i += 512) smp[OF_C + i] = 0.f;
    for (int i = tid; i < 2560; i += 512) smp[OF_HS + i] = 0.f;
    if (tid < 128) smp[OF_CS + tid] = 0.f;

    // push targets for rows r = r0 + 2*rq + i (i = 0,1)
    unsigned htg[2][2];
    unsigned ctg = 0;
#pragma unroll
    for (int i = 0; i < 2; i++) {
        int r = r0 + rq * 2 + i;
        htg[i][0] = 0; htg[i][1] = 0;
        int n = 0;
#pragma unroll
        for (int rg2 = 0; rg2 < 4; rg2++) {
            int v = r + 1 - 4 * rg2;
            if (v >= 0) {
                int mm = v >> 4, ii = v & 15;
                if (mm < 4 && ii < 5)
                    htg[i][n++] = mapa_rank(sbase + OF_HS * 4, rg2)
                                  + ((mm * 5 + ii) * 64 + j) * 4;
            }
        }
    }
    if (rq == 7 && rg < 3) ctg = mapa_rank(sbase + OF_CS * 4, rg + 1) + j * 4;

    unsigned wq = sbase + OF_WC * 4 + j * 16;  // + kp*1024

    for (int t = 0; t < NWD; t++) {
        int p = t & 1, np = 1 - p;

        // prefetch xi at CONSUMER coordinates: gate rows q_g = q0 + 16g + aA,
        // columns ooA / ooB (shared window w per g since aA == aB)
        float xg[8];
#pragma unroll
        for (int g = 0; g < 4; g++) {
            int qg = q0 + 16 * g + aA;
            int w = t - qg;
            bool in = (unsigned)w < 64u;
            const float* pa = g_i2s + ((((b << 6) | qg) << 6 | (w & 63)) << 8);
            xg[g]     = in ? pa[ooA] : biA;
            xg[4 + g] = in ? pa[ooB] : biB;
        }

        CLUSTER_SYNC();  // pushes from step t-1 visible; stage[p], c_st[p] ready

        // ---- phase 1 partials: 16 gate rows over this k-half ----
        {
            unsigned hbB = sbase + (OF_HS + p * 1280) * 4 + kh * 128;
#pragma unroll
            for (int m = 0; m < 4; m++) {
                u64t a0 = 0, a1 = 0, a2 = 0, a3 = 0;
                unsigned hb = hbB + m * 1280;
#pragma unroll
                for (int k4 = 0; k4 < 8; k4++) {
                    u64t A0,A1,B0,B1,C0,C1,D0,D1,E0,E1;
                    lds2(A0, A1, hb + k4*16);
                    lds2(B0, B1, hb + 256 + k4*16);
                    lds2(C0, C1, hb + 512 + k4*16);
                    lds2(D0, D1, hb + 768 + k4*16);
                    lds2(E0, E1, hb + 1024 + k4*16);
                    int kp = 2 * k4;
                    fma2(a0, A0, wp0[kp]);   fma2(a0, B0, wp1[kp]);
                    fma2(a1, B0, wp0[kp]);   fma2(a1, C0, wp1[kp]);
                    fma2(a2, C0, wp0[kp]);   fma2(a2, D0, wp1[kp]);
                    fma2(a3, D0, wp0[kp]);   fma2(a3, E0, wp1[kp]);
                    fma2(a0, A1, wp0[kp+1]); fma2(a0, B1, wp1[kp+1]);
                    fma2(a1, B1, wp0[kp+1]); fma2(a1, C1, wp1[kp+1]);
                    fma2(a2, C1, wp0[kp+1]); fma2(a2, D1, wp1[kp+1]);
                    fma2(a3, D1, wp0[kp+1]); fma2(a3, E1, wp1[kp+1]);
                }
                float2 u;
                int base = OF_P1 + kh * 4096 + (m * 4) * 256 + o;
                u = upk(a0); smp[base]       = u.x + u.y;
                u = upk(a1); smp[base + 256] = u.x + u.y;
                u = upk(a2); smp[base + 512] = u.x + u.y;
                u = upk(a3); smp[base + 768] = u.x + u.y;
            }
        }

        // ---- phase 2 partials: quad rows over this k-half ----
        {
            int rl0 = quad * 4;
            unsigned cb = sbase + (OF_C + (p << 10)) * 4;
            unsigned a_m1 = (rl0 == 0) ? (sbase + (OF_CS + p * 64) * 4 + kh * 128)
                                       : (cb + (rl0 - 1) * 256 + kh * 128);
            unsigned a_0 = cb + rl0 * 256 + kh * 128;
            int kpbase = kh * 16;
            u64t ac0 = 0, ac1 = 0, ac2 = 0, ac3 = 0;
#pragma unroll
            for (int k4 = 0; k4 < 8; k4++) {
                u64t w0A, w1A, w0B, w1B;
                lds2(w0A, w1A, wq + (kpbase + 2*k4) * 1024);
                lds2(w0B, w1B, wq + (kpbase + 2*k4 + 1) * 1024);
                u64t m0,m1, r00,r01, r10,r11, r20,r21, r30,r31;
                lds2(m0,  m1,  a_m1 + k4*16);
                lds2(r00, r01, a_0 + k4*16);
                lds2(r10, r11, a_0 + 256 + k4*16);
                lds2(r20, r21, a_0 + 512 + k4*16);
                lds2(r30, r31, a_0 + 768 + k4*16);
                fma2(ac0, m0,  w0A); fma2(ac0, r00, w1A);
                fma2(ac1, r00, w0A); fma2(ac1, r10, w1A);
                fma2(ac2, r10, w0A); fma2(ac2, r20, w1A);
                fma2(ac3, r20, w0A); fma2(ac3, r30, w1A);
                fma2(ac0, m1,  w0B); fma2(ac0, r01, w1B);
                fma2(ac1, r01, w0B); fma2(ac1, r11, w1B);
                fma2(ac2, r11, w0B); fma2(ac2, r21, w1B);
                fma2(ac3, r21, w0B); fma2(ac3, r31, w1B);
            }
            float2 u;
            int base = OF_P2 + kh * 1024 + rl0 * 64 + j;
            u = upk(ac0); smp[base]       = u.x + u.y;
            u = upk(ac1); smp[base + 64]  = u.x + u.y;
            u = upk(ac2); smp[base + 128] = u.x + u.y;
            u = upk(ac3); smp[base + 192] = u.x + u.y;
        }
        __syncthreads();  // P1, P2 visible

        // ---- fused combine: gates + cell/hidden update + pushes ----
        {
            unsigned hpoff = np * 1280 * 4;
#pragma unroll
            for (int i = 0; i < 2; i++) {
                int rl = 2 * rq + i;
                int r = r0 + rl;
                int oo = i ? ooB : ooA;
                float bsv = i ? bsB : bsA;
                float acc = bcj + smp[OF_P2 + rl * 64 + j]
                                + smp[OF_P2 + 1024 + rl * 64 + j];
                float gate[4];
#pragma unroll
                for (int g = 0; g < 4; g++) {
                    int lr = g * 4 + aA;
                    float pv = smp[OF_P1 + lr * 256 + oo]
                             + smp[OF_P1 + 4096 + lr * 256 + oo];
                    gate[g] = sig_(xg[i * 4 + g] + bsv + pv);
                }
                float cv = gate[2] * acc + gate[0] * gate[1];
                float hv = gate[3] * tanh_(cv);
                smp[OF_C + (np << 10) + rl * 64 + j] = cv;
                if (htg[i][0]) stsc(htg[i][0] + hpoff, hv);
                if (htg[i][1]) stsc(htg[i][1] + hpoff, hv);
                if (i == 1 && ctg) stsc(ctg + np * 256, cv);
                int w = t - r;
                if ((unsigned)w < 64u)
                    g_hbuf[((((b << 6) | r) << 6 | w) << 6) | j] = hv;
            }
        }
    }

    CLUSTER_SYNC();  // exit-race guard for in-flight cluster stores
}

// ---------------------------------------------------------------------------
// up (unchanged)
// ---------------------------------------------------------------------------
#define UP_SMEM_BYTES ((4096 + 128 * 65) * 4)

__global__ __launch_bounds__(256) void up_kernel(const float* __restrict__ w_up,
                                                 const float* __restrict__ b_up,
                                                 float* __restrict__ out) {
    extern __shared__ float us[];
    float* hsm = us;
    float* osm = us + 4096;
    unsigned hbase = smem_u32(us);
    int b = blockIdx.x >> 6, r = blockIdx.x & 63;
    int tid = threadIdx.x;
    const float* src = g_hbuf + (((b << 6) | r) << 12);
    for (int i = tid; i < 4096; i += 256) hsm[i] = src[i];
    __syncthreads();

    int oc = tid & 127, wh = tid >> 7;
    u64t uu[32];
    const float4* pu = (const float4*)(w_up + (oc << 6));
#pragma unroll
    for (int k4 = 0; k4 < 16; k4++) {
        float4 v = pu[k4];
        uu[2*k4]     = pk(v.x, v.y);
        uu[2*k4 + 1] = pk(v.z, v.w);
    }
    float bu = b_up[oc];
    for (int w = (wh << 5); w < (wh << 5) + 32; w++) {
        u64t a = pk(bu, 0.f);
        unsigned hr = hbase + (w << 8);
#pragma unroll
        for (int k4 = 0; k4 < 16; k4++) {
            u64t x0, x1;
            lds2(x0, x1, hr + k4*16);
            fma2(a, x0, uu[2*k4]);
            fma2(a, x1, uu[2*k4 + 1]);
        }
        float2 f = upk(a);
        osm[oc * 65 + w] = f.x + f.y;
    }
    __syncthreads();

    float* ob = out + (((b << 7) << 6 | r) << 6);
    for (int i = tid; i < 8192; i += 256) {
        int oc2 = i >> 6, w = i & 63;
        ob[(oc2 << 12) | w] = osm[oc2 * 65 + w];
    }
}

extern "C" void kernel_launch(void* const* d_in, const int* in_sizes, int n_in,
                              void* d_out, int out_size) {
    const float* inputs = (const float*)d_in[0];
    const float* w_i2s  = (const float*)d_in[1];
    const float* b_i2s  = (const float*)d_in[2];
    const float* w_s2s  = (const float*)d_in[3];
    const float* b_s2s  = (const float*)d_in[4];
    const float* w_c2c  = (const float*)d_in[5];
    const float* b_c2c  = (const float*)d_in[6];
    const float* w_up   = (const float*)d_in[7];
    const float* b_up   = (const float*)d_in[8];
    float* out = (float*)d_out;

    cudaFuncSetAttribute(scan_kernel, cudaFuncAttributeMaxDynamicSharedMemorySize, SCAN_SMEM_BYTES);
    cudaFuncSetAttribute(up_kernel, cudaFuncAttributeMaxDynamicSharedMemorySize, UP_SMEM_BYTES);

    i2s_kernel<<<1024, 256>>>(inputs, w_i2s, b_i2s);
    scan_kernel<<<128, 512, SCAN_SMEM_BYTES>>>(w_s2s, b_s2s, w_c2c, b_c2c, b_i2s);
    up_kernel<<<2048, 256, UP_SMEM_BYTES>>>(w_up, b_up, out);
}

// round 15
// speedup vs baseline: 2.7466x; 1.0255x over previous
#include <cuda_runtime.h>
#include <cuda_bf16.h>

#define BB 32
#define NWD 127

__device__ float g_i2s[BB * 64 * 64 * 256];   // [b][r][w][o] (includes b_i2s)
__device__ float g_hbuf[BB * 64 * 64 * 64];   // [b][r][w][j]
__device__ __nv_bfloat16 g_wbf[2 * 256 * 64]; // [hi/lo][o][c]

typedef unsigned long long u64t;

__device__ __forceinline__ float sig_(float x) { return 1.0f / (1.0f + __expf(-x)); }
__device__ __forceinline__ float tanh_(float x) {
    float e = __expf(-2.0f * x);
    return __fdividef(1.0f - e, 1.0f + e);
}
__device__ __forceinline__ u64t pk(float lo, float hi) {
    u64t r; asm("mov.b64 %0, {%1,%2};" : "=l"(r) : "f"(lo), "f"(hi)); return r;
}
__device__ __forceinline__ float2 upk(u64t v) {
    float2 r; asm("mov.b64 {%0,%1}, %2;" : "=f"(r.x), "=f"(r.y) : "l"(v)); return r;
}
__device__ __forceinline__ void fma2(u64t& d, u64t a, u64t b) {
    asm("fma.rn.f32x2 %0, %1, %2, %0;" : "+l"(d) : "l"(a), "l"(b));
}
__device__ __forceinline__ void lds2(u64t& a, u64t& b, unsigned addr) {
    asm volatile("ld.shared.v2.u64 {%0,%1}, [%2];" : "=l"(a), "=l"(b) : "r"(addr));
}
__device__ __forceinline__ unsigned lds32(unsigned addr) {
    unsigned v;
    asm volatile("ld.shared.b32 %0, [%1];" : "=r"(v) : "r"(addr));
    return v;
}
__device__ __forceinline__ unsigned smem_u32(const void* p) {
    return (unsigned)__cvta_generic_to_shared(p);
}
__device__ __forceinline__ unsigned mapa_rank(unsigned addr, int rank) {
    unsigned r;
    asm("mapa.shared::cluster.u32 %0, %1, %2;" : "=r"(r) : "r"(addr), "r"(rank));
    return r;
}
__device__ __forceinline__ void stsc(unsigned addr, float v) {
    asm volatile("st.shared::cluster.f32 [%0], %1;" :: "r"(addr), "f"(v) : "memory");
}
#define CLUSTER_SYNC() do { \
    asm volatile("barrier.cluster.arrive.aligned;" ::: "memory"); \
    asm volatile("barrier.cluster.wait.aligned;" ::: "memory"); \
} while (0)

__device__ __forceinline__ void mma_bf16(float* d, unsigned a0, unsigned a1,
                                         unsigned a2, unsigned a3,
                                         unsigned b0, unsigned b1) {
    asm volatile(
        "mma.sync.aligned.m16n8k16.row.col.f32.bf16.bf16.f32 "
        "{%0,%1,%2,%3}, {%4,%5,%6,%7}, {%8,%9}, {%0,%1,%2,%3};"
        : "+f"(d[0]), "+f"(d[1]), "+f"(d[2]), "+f"(d[3])
        : "r"(a0), "r"(a1), "r"(a2), "r"(a3), "r"(b0), "r"(b1));
}

// ---------------------------------------------------------------------------
// prep: split w_i2s into bf16 hi/lo
// ---------------------------------------------------------------------------
__global__ void prep_w(const float* __restrict__ w_i2s) {
    int i = blockIdx.x * 256 + threadIdx.x;  // 16384
    float x = w_i2s[i];
    __nv_bfloat16 hi = __float2bfloat16(x);
    g_wbf[i] = hi;
    g_wbf[16384 + i] = __float2bfloat16(x - __bfloat162float(hi));
}

// ---------------------------------------------------------------------------
// i2s via mma.sync bf16 hi/lo (3 products, fp32 acc in regs).
// block = (b, r): M=64 (w), N=256 (o), K=64 (c). 8 warps = 4 mtiles x 2 nhalves.
// smem rows padded to 144 B (36 words) -> all fragment loads conflict-free.
// byte offsets:
#define XH_B   0            // [64][72 bf16]  9216 B
#define XL_B   9216
#define WH_B   18432        // [256][72 bf16] 36864 B
#define WL_B   55296
#define BIAS_B 92160        // 256 floats
#define I2S_SMEM 93184
// ---------------------------------------------------------------------------
__global__ __launch_bounds__(256, 2) void i2s_mma(const float* __restrict__ inputs,
                                                  const float* __restrict__ b_i2s) {
    extern __shared__ char ism[];
    unsigned sb = smem_u32(ism);
    unsigned* ismw = (unsigned*)ism;
    float* bias = (float*)(ism + BIAS_B);
    int b = blockIdx.x >> 6, r = blockIdx.x & 63;
    int tid = threadIdx.x;

    // stage X hi/lo: element (w, c) at row w*144 + c*2
    for (int i = tid; i < 4096; i += 256) {
        int c = i >> 6, w = i & 63;
        float x = inputs[((((b << 6) | c) << 6 | r) << 6) | w];
        __nv_bfloat16 h = __float2bfloat16(x);
        __nv_bfloat16 l = __float2bfloat16(x - __bfloat162float(h));
        *(__nv_bfloat16*)(ism + XH_B + w * 144 + c * 2) = h;
        *(__nv_bfloat16*)(ism + XL_B + w * 144 + c * 2) = l;
    }
    // stage W hi/lo: row o (64 bf16 = 32 words) -> padded rows of 36 words
    for (int i = tid; i < 8192; i += 256) {
        int o = i >> 5, cw = i & 31;
        ismw[(WH_B >> 2) + o * 36 + cw] = ((const unsigned*)g_wbf)[o * 32 + cw];
        ismw[(WL_B >> 2) + o * 36 + cw] = ((const unsigned*)g_wbf)[8192 + o * 32 + cw];
    }
    bias[tid] = b_i2s[tid];
    __syncthreads();

    int wid = tid >> 5, lane = tid & 31;
    int mtile = wid & 3, nhalf = wid >> 2;
    int lq = lane >> 2, l4 = lane & 3;

    float acc[16][4];
#pragma unroll
    for (int nt = 0; nt < 16; nt++) {
        acc[nt][0] = 0.f; acc[nt][1] = 0.f; acc[nt][2] = 0.f; acc[nt][3] = 0.f;
    }

    // A fragment row bases (byte): rows mtile*16+lq and +8, col byte l4*4
    unsigned ax0h = sb + XH_B + (mtile * 16 + lq) * 144 + l4 * 4;
    unsigned ax8h = ax0h + 8 * 144;
    unsigned ax0l = ax0h + (XL_B - XH_B);
    unsigned ax8l = ax8h + (XL_B - XH_B);
    // B row base for this thread's col group: o = nhalf*128 + nt*8 + lq
    unsigned bwh = sb + WH_B + (nhalf * 128 + lq) * 144 + l4 * 4;
    unsigned bwl = bwh + (WL_B - WH_B);

#pragma unroll
    for (int pass = 0; pass < 3; pass++) {
        unsigned a0b = (pass < 2) ? ax0h : ax0l;
        unsigned a8b = (pass < 2) ? ax8h : ax8l;
        unsigned bb  = (pass == 1) ? bwl : bwh;
#pragma unroll
        for (int ks = 0; ks < 4; ks++) {
            unsigned a0 = lds32(a0b + ks * 32);
            unsigned a1 = lds32(a8b + ks * 32);
            unsigned a2 = lds32(a0b + ks * 32 + 16);
            unsigned a3 = lds32(a8b + ks * 32 + 16);
#pragma unroll
            for (int nt = 0; nt < 16; nt++) {
                unsigned baddr = bb + nt * 8 * 144 + ks * 32;
                unsigned b0 = lds32(baddr);
                unsigned b1 = lds32(baddr + 16);
                mma_bf16(acc[nt], a0, a1, a2, a3, b0, b1);
            }
        }
    }

    // epilogue: C frag -> g_i2s[b][r][w][o] + bias (STG.64 pairs)
    int w0 = mtile * 16 + lq;
    float* ob = g_i2s + ((((b << 6) | r) << 6) << 8);
#pragma unroll
    for (int nt = 0; nt < 16; nt++) {
        int o = nhalf * 128 + nt * 8 + 2 * l4;
        float b0v = bias[o], b1v = bias[o + 1];
        float2 v0 = make_float2(acc[nt][0] + b0v, acc[nt][1] + b1v);
        float2 v1 = make_float2(acc[nt][2] + b0v, acc[nt][3] + b1v);
        *(float2*)(ob + (w0 << 8) + o) = v0;
        *(float2*)(ob + ((w0 + 8) << 8) + o) = v1;
    }
}

// ---------------------------------------------------------------------------
// persistent scan (IDENTICAL to round-10 passing version)
// ---------------------------------------------------------------------------
#define OF_C    0
#define OF_HS   2048
#define OF_CS   4608
#define OF_P1   4736
#define OF_P2   12928
#define OF_WC   14976
#define SCAN_SMEM_BYTES (23168 * 4)

__global__ void __cluster_dims__(4, 1, 1) __launch_bounds__(512, 1)
scan_kernel(const float* __restrict__ w_s2s,
            const float* __restrict__ b_s2s,
            const float* __restrict__ w_c2c,
            const float* __restrict__ b_c2c,
            const float* __restrict__ b_i2s) {
    extern __shared__ float smp[];
    unsigned sbase = smem_u32(smp);

    int b = blockIdx.x >> 2, rg = blockIdx.x & 3;
    int r0 = rg << 4, q0 = rg << 2;
    int tid = threadIdx.x;
    int o = tid & 255, kh = tid >> 8;
    int j = tid & 63, g6 = tid >> 6;
    int quad = g6 & 3;
    int rq = g6;

    u64t wp0[16], wp1[16];
    {
        const float4* wp = (const float4*)(w_s2s + o * 128 + kh * 64);
#pragma unroll
        for (int k2 = 0; k2 < 16; k2++) {
            float4 v = wp[k2];
            wp0[k2] = pk(v.x, v.z);
            wp1[k2] = pk(v.y, v.w);
        }
    }
    float bcj = b_c2c[j];

    int rlA = 2 * rq, rlB = 2 * rq + 1;
    int aA = rlA >> 2;
    int ooA = ((rlA & 3) << 6) | j;
    int ooB = ((rlB & 3) << 6) | j;
    float bsA = b_s2s[ooA], bsB = b_s2s[ooB];
    float biA = b_i2s[ooA], biB = b_i2s[ooB];

    for (int i = tid; i < 8192; i += 512) {
        int kp = i >> 8, rr = i & 255, j2 = rr >> 2, s = (rr >> 1) & 1, e = rr & 1;
        smp[OF_WC + i] = w_c2c[(j2 * 64 + 2 * kp + e) * 2 + s];
    }
    for (int i = tid; i < 1024; i += 512) smp[OF_C + i] = 0.f;
    for (int i = tid; i < 2560; i += 512) smp[OF_HS + i] = 0.f;
    if (tid < 128) smp[OF_CS + tid] = 0.f;

    unsigned htg[2][2];
    unsigned ctg = 0;
#pragma unroll
    for (int i = 0; i < 2; i++) {
        int r = r0 + rq * 2 + i;
        htg[i][0] = 0; htg[i][1] = 0;
        int n = 0;
#pragma unroll
        for (int rg2 = 0; rg2 < 4; rg2++) {
            int v = r + 1 - 4 * rg2;
            if (v >= 0) {
                int mm = v >> 4, ii = v & 15;
                if (mm < 4 && ii < 5)
                    htg[i][n++] = mapa_rank(sbase + OF_HS * 4, rg2)
                                  + ((mm * 5 + ii) * 64 + j) * 4;
            }
        }
    }
    if (rq == 7 && rg < 3) ctg = mapa_rank(sbase + OF_CS * 4, rg + 1) + j * 4;

    unsigned wq = sbase + OF_WC * 4 + j * 16;

    for (int t = 0; t < NWD; t++) {
        int p = t & 1, np = 1 - p;

        float xg[8];
#pragma unroll
        for (int g = 0; g < 4; g++) {
            int qg = q0 + 16 * g + aA;
            int w = t - qg;
            bool in = (unsigned)w < 64u;
            const float* pa = g_i2s + ((((b << 6) | qg) << 6 | (w & 63)) << 8);
            xg[g]     = in ? pa[ooA] : biA;
            xg[4 + g] = in ? pa[ooB] : biB;
        }

        CLUSTER_SYNC();

        {
            unsigned hbB = sbase + (OF_HS + p * 1280) * 4 + kh * 128;
#pragma unroll
            for (int m = 0; m < 4; m++) {
                u64t a0 = 0, a1 = 0, a2 = 0, a3 = 0;
                unsigned hb = hbB + m * 1280;
#pragma unroll
                for (int k4 = 0; k4 < 8; k4++) {
                    u64t A0,A1,B0,B1,C0,C1,D0,D1,E0,E1;
                    lds2(A0, A1, hb + k4*16);
                    lds2(B0, B1, hb + 256 + k4*16);
                    lds2(C0, C1, hb + 512 + k4*16);
                    lds2(D0, D1, hb + 768 + k4*16);
                    lds2(E0, E1, hb + 1024 + k4*16);
                    int kp = 2 * k4;
                    fma2(a0, A0, wp0[kp]);   fma2(a0, B0, wp1[kp]);
                    fma2(a1, B0, wp0[kp]);   fma2(a1, C0, wp1[kp]);
                    fma2(a2, C0, wp0[kp]);   fma2(a2, D0, wp1[kp]);
                    fma2(a3, D0, wp0[kp]);   fma2(a3, E0, wp1[kp]);
                    fma2(a0, A1, wp0[kp+1]); fma2(a0, B1, wp1[kp+1]);
                    fma2(a1, B1, wp0[kp+1]); fma2(a1, C1, wp1[kp+1]);
                    fma2(a2, C1, wp0[kp+1]); fma2(a2, D1, wp1[kp+1]);
                    fma2(a3, D1, wp0[kp+1]); fma2(a3, E1, wp1[kp+1]);
                }
                float2 u;
                int base = OF_P1 + kh * 4096 + (m * 4) * 256 + o;
                u = upk(a0); smp[base]       = u.x + u.y;
                u = upk(a1); smp[base + 256] = u.x + u.y;
                u = upk(a2); smp[base + 512] = u.x + u.y;
                u = upk(a3); smp[base + 768] = u.x + u.y;
            }
        }

        {
            int rl0 = quad * 4;
            unsigned cb = sbase + (OF_C + (p << 10)) * 4;
            unsigned a_m1 = (rl0 == 0) ? (sbase + (OF_CS + p * 64) * 4 + kh * 128)
                                       : (cb + (rl0 - 1) * 256 + kh * 128);
            unsigned a_0 = cb + rl0 * 256 + kh * 128;
            int kpbase = kh * 16;
            u64t ac0 = 0, ac1 = 0, ac2 = 0, ac3 = 0;
#pragma unroll
            for (int k4 = 0; k4 < 8; k4++) {
                u64t w0A, w1A, w0B, w1B;
                lds2(w0A, w1A, wq + (kpbase + 2*k4) * 1024);
                lds2(w0B, w1B, wq + (kpbase + 2*k4 + 1) * 1024);
                u64t m0,m1, r00,r01, r10,r11, r20,r21, r30,r31;
                lds2(m0,  m1,  a_m1 + k4*16);
                lds2(r00, r01, a_0 + k4*16);
                lds2(r10, r11, a_0 + 256 + k4*16);
                lds2(r20, r21, a_0 + 512 + k4*16);
                lds2(r30, r31, a_0 + 768 + k4*16);
                fma2(ac0, m0,  w0A); fma2(ac0, r00, w1A);
                fma2(ac1, r00, w0A); fma2(ac1, r10, w1A);
                fma2(ac2, r10, w0A); fma2(ac2, r20, w1A);
                fma2(ac3, r20, w0A); fma2(ac3, r30, w1A);
                fma2(ac0, m1,  w0B); fma2(ac0, r01, w1B);
                fma2(ac1, r01, w0B); fma2(ac1, r11, w1B);
                fma2(ac2, r11, w0B); fma2(ac2, r21, w1B);
                fma2(ac3, r21, w0B); fma2(ac3, r31, w1B);
            }
            float2 u;
            int base = OF_P2 + kh * 1024 + rl0 * 64 + j;
            u = upk(ac0); smp[base]       = u.x + u.y;
            u = upk(ac1); smp[base + 64]  = u.x + u.y;
            u = upk(ac2); smp[base + 128] = u.x + u.y;
            u = upk(ac3); smp[base + 192] = u.x + u.y;
        }
        __syncthreads();

        {
            unsigned hpoff = np * 1280 * 4;
#pragma unroll
            for (int i = 0; i < 2; i++) {
                int rl = 2 * rq + i;
                int r = r0 + rl;
                int oo = i ? ooB : ooA;
                float bsv = i ? bsB : bsA;
                float acc = bcj + smp[OF_P2 + rl * 64 + j]
                                + smp[OF_P2 + 1024 + rl * 64 + j];
                float gate[4];
#pragma unroll
                for (int g = 0; g < 4; g++) {
                    int lr = g * 4 + aA;
                    float pv = smp[OF_P1 + lr * 256 + oo]
                             + smp[OF_P1 + 4096 + lr * 256 + oo];
                    gate[g] = sig_(xg[i * 4 + g] + bsv + pv);
                }
                float cv = gate[2] * acc + gate[0] * gate[1];
                float hv = gate[3] * tanh_(cv);
                smp[OF_C + (np << 10) + rl * 64 + j] = cv;
                if (htg[i][0]) stsc(htg[i][0] + hpoff, hv);
                if (htg[i][1]) stsc(htg[i][1] + hpoff, hv);
                if (i == 1 && ctg) stsc(ctg + np * 256, cv);
                int w = t - r;
                if ((unsigned)w < 64u)
                    g_hbuf[((((b << 6) | r) << 6 | w) << 6) | j] = hv;
            }
        }
    }

    CLUSTER_SYNC();
}

// ---------------------------------------------------------------------------
// up (unchanged)
// ---------------------------------------------------------------------------
#define UP_SMEM_BYTES ((4096 + 128 * 65) * 4)

__global__ __launch_bounds__(256) void up_kernel(const float* __restrict__ w_up,
                                                 const float* __restrict__ b_up,
                                                 float* __restrict__ out) {
    extern __shared__ float us[];
    float* hsm = us;
    float* osm = us + 4096;
    unsigned hbase = smem_u32(us);
    int b = blockIdx.x >> 6, r = blockIdx.x & 63;
    int tid = threadIdx.x;
    const float* src = g_hbuf + (((b << 6) | r) << 12);
    for (int i = tid; i < 4096; i += 256) hsm[i] = src[i];
    __syncthreads();

    int oc = tid & 127, wh = tid >> 7;
    u64t uu[32];
    const float4* pu = (const float4*)(w_up + (oc << 6));
#pragma unroll
    for (int k4 = 0; k4 < 16; k4++) {
        float4 v = pu[k4];
        uu[2*k4]     = pk(v.x, v.y);
        uu[2*k4 + 1] = pk(v.z, v.w);
    }
    float bu = b_up[oc];
    for (int w = (wh << 5); w < (wh << 5) + 32; w++) {
        u64t a = pk(bu, 0.f);
        unsigned hr = hbase + (w << 8);
#pragma unroll
        for (int k4 = 0; k4 < 16; k4++) {
            u64t x0, x1;
            lds2(x0, x1, hr + k4*16);
            fma2(a, x0, uu[2*k4]);
            fma2(a, x1, uu[2*k4 + 1]);
        }
        float2 f = upk(a);
        osm[oc * 65 + w] = f.x + f.y;
    }
    __syncthreads();

    float* ob = out + (((b << 7) << 6 | r) << 6);
    for (int i = tid; i < 8192; i += 256) {
        int oc2 = i >> 6, w = i & 63;
        ob[(oc2 << 12) | w] = osm[oc2 * 65 + w];
    }
}

extern "C" void kernel_launch(void* const* d_in, const int* in_sizes, int n_in,
                              void* d_out, int out_size) {
    const float* inputs = (const float*)d_in[0];
    const float* w_i2s  = (const float*)d_in[1];
    const float* b_i2s  = (const float*)d_in[2];
    const float* w_s2s  = (const float*)d_in[3];
    const float* b_s2s  = (const float*)d_in[4];
    const float* w_c2c  = (const float*)d_in[5];
    const float* b_c2c  = (const float*)d_in[6];
    const float* w_up   = (const float*)d_in[7];
    const float* b_up   = (const float*)d_in[8];
    float* out = (float*)d_out;

    cudaFuncSetAttribute(i2s_mma, cudaFuncAttributeMaxDynamicSharedMemorySize, I2S_SMEM);
    cudaFuncSetAttribute(scan_kernel, cudaFuncAttributeMaxDynamicSharedMemorySize, SCAN_SMEM_BYTES);
    cudaFuncSetAttribute(up_kernel, cudaFuncAttributeMaxDynamicSharedMemorySize, UP_SMEM_BYTES);

    prep_w<<<64, 256>>>(w_i2s);
    i2s_mma<<<2048, 256, I2S_SMEM>>>(inputs, b_i2s);
    scan_kernel<<<128, 512, SCAN_SMEM_BYTES>>>(w_s2s, b_s2s, w_c2c, b_c2c, b_i2s);
    up_kernel<<<2048, 256, UP_SMEM_BYTES>>>(w_up, b_up, out);
}

// round 16
// speedup vs baseline: 2.8619x; 1.0420x over previous
#include <cuda_runtime.h>
#include <cuda_bf16.h>

#define BB 32
#define NWD 127

__device__ float g_i2s[BB * 64 * 64 * 256];   // [b][r][w][o] (includes b_i2s)
__device__ float g_hbuf[BB * 64 * 64 * 64];   // [b][r][w][j]
__device__ __nv_bfloat16 g_wbf[2 * 256 * 64]; // [hi/lo][o][c]   (w_i2s)
__device__ __nv_bfloat16 g_ubf[2 * 128 * 64]; // [hi/lo][oc][j]  (w_up)

typedef unsigned long long u64t;

__device__ __forceinline__ float sig_(float x) { return 1.0f / (1.0f + __expf(-x)); }
__device__ __forceinline__ float tanh_(float x) {
    float e = __expf(-2.0f * x);
    return __fdividef(1.0f - e, 1.0f + e);
}
__device__ __forceinline__ u64t pk(float lo, float hi) {
    u64t r; asm("mov.b64 %0, {%1,%2};" : "=l"(r) : "f"(lo), "f"(hi)); return r;
}
__device__ __forceinline__ float2 upk(u64t v) {
    float2 r; asm("mov.b64 {%0,%1}, %2;" : "=f"(r.x), "=f"(r.y) : "l"(v)); return r;
}
__device__ __forceinline__ void fma2(u64t& d, u64t a, u64t b) {
    asm("fma.rn.f32x2 %0, %1, %2, %0;" : "+l"(d) : "l"(a), "l"(b));
}
__device__ __forceinline__ void lds2(u64t& a, u64t& b, unsigned addr) {
    asm volatile("ld.shared.v2.u64 {%0,%1}, [%2];" : "=l"(a), "=l"(b) : "r"(addr));
}
__device__ __forceinline__ unsigned lds32(unsigned addr) {
    unsigned v;
    asm volatile("ld.shared.b32 %0, [%1];" : "=r"(v) : "r"(addr));
    return v;
}
__device__ __forceinline__ unsigned smem_u32(const void* p) {
    return (unsigned)__cvta_generic_to_shared(p);
}
__device__ __forceinline__ unsigned mapa_rank(unsigned addr, int rank) {
    unsigned r;
    asm("mapa.shared::cluster.u32 %0, %1, %2;" : "=r"(r) : "r"(addr), "r"(rank));
    return r;
}
__device__ __forceinline__ void stsc(unsigned addr, float v) {
    asm volatile("st.shared::cluster.f32 [%0], %1;" :: "r"(addr), "f"(v) : "memory");
}
#define CLUSTER_SYNC() do { \
    asm volatile("barrier.cluster.arrive.aligned;" ::: "memory"); \
    asm volatile("barrier.cluster.wait.aligned;" ::: "memory"); \
} while (0)

__device__ __forceinline__ void mma_bf16(float* d, unsigned a0, unsigned a1,
                                         unsigned a2, unsigned a3,
                                         unsigned b0, unsigned b1) {
    asm volatile(
        "mma.sync.aligned.m16n8k16.row.col.f32.bf16.bf16.f32 "
        "{%0,%1,%2,%3}, {%4,%5,%6,%7}, {%8,%9}, {%0,%1,%2,%3};"
        : "+f"(d[0]), "+f"(d[1]), "+f"(d[2]), "+f"(d[3])
        : "r"(a0), "r"(a1), "r"(a2), "r"(a3), "r"(b0), "r"(b1));
}

// ---------------------------------------------------------------------------
// prep: split w_i2s (16384) and w_up (8192) into bf16 hi/lo
// ---------------------------------------------------------------------------
__global__ void prep_w(const float* __restrict__ w_i2s,
                       const float* __restrict__ w_up) {
    int i = blockIdx.x * 256 + threadIdx.x;  // 24576
    if (i < 16384) {
        float x = w_i2s[i];
        __nv_bfloat16 hi = __float2bfloat16(x);
        g_wbf[i] = hi;
        g_wbf[16384 + i] = __float2bfloat16(x - __bfloat162float(hi));
    } else {
        int k = i - 16384;
        float x = w_up[k];
        __nv_bfloat16 hi = __float2bfloat16(x);
        g_ubf[k] = hi;
        g_ubf[8192 + k] = __float2bfloat16(x - __bfloat162float(hi));
    }
}

// ---------------------------------------------------------------------------
// i2s via mma.sync bf16 hi/lo (unchanged from passing R15)
// ---------------------------------------------------------------------------
#define XH_B   0
#define XL_B   9216
#define WH_B   18432
#define WL_B   55296
#define BIAS_B 92160
#define I2S_SMEM 93184

__global__ __launch_bounds__(256, 2) void i2s_mma(const float* __restrict__ inputs,
                                                  const float* __restrict__ b_i2s) {
    extern __shared__ char ism[];
    unsigned sb = smem_u32(ism);
    unsigned* ismw = (unsigned*)ism;
    float* bias = (float*)(ism + BIAS_B);
    int b = blockIdx.x >> 6, r = blockIdx.x & 63;
    int tid = threadIdx.x;

    for (int i = tid; i < 4096; i += 256) {
        int c = i >> 6, w = i & 63;
        float x = inputs[((((b << 6) | c) << 6 | r) << 6) | w];
        __nv_bfloat16 h = __float2bfloat16(x);
        __nv_bfloat16 l = __float2bfloat16(x - __bfloat162float(h));
        *(__nv_bfloat16*)(ism + XH_B + w * 144 + c * 2) = h;
        *(__nv_bfloat16*)(ism + XL_B + w * 144 + c * 2) = l;
    }
    for (int i = tid; i < 8192; i += 256) {
        int o = i >> 5, cw = i & 31;
        ismw[(WH_B >> 2) + o * 36 + cw] = ((const unsigned*)g_wbf)[o * 32 + cw];
        ismw[(WL_B >> 2) + o * 36 + cw] = ((const unsigned*)g_wbf)[8192 + o * 32 + cw];
    }
    bias[tid] = b_i2s[tid];
    __syncthreads();

    int wid = tid >> 5, lane = tid & 31;
    int mtile = wid & 3, nhalf = wid >> 2;
    int lq = lane >> 2, l4 = lane & 3;

    float acc[16][4];
#pragma unroll
    for (int nt = 0; nt < 16; nt++) {
        acc[nt][0] = 0.f; acc[nt][1] = 0.f; acc[nt][2] = 0.f; acc[nt][3] = 0.f;
    }

    unsigned ax0h = sb + XH_B + (mtile * 16 + lq) * 144 + l4 * 4;
    unsigned ax8h = ax0h + 8 * 144;
    unsigned ax0l = ax0h + (XL_B - XH_B);
    unsigned ax8l = ax8h + (XL_B - XH_B);
    unsigned bwh = sb + WH_B + (nhalf * 128 + lq) * 144 + l4 * 4;
    unsigned bwl = bwh + (WL_B - WH_B);

#pragma unroll
    for (int pass = 0; pass < 3; pass++) {
        unsigned a0b = (pass < 2) ? ax0h : ax0l;
        unsigned a8b = (pass < 2) ? ax8h : ax8l;
        unsigned bb  = (pass == 1) ? bwl : bwh;
#pragma unroll
        for (int ks = 0; ks < 4; ks++) {
            unsigned a0 = lds32(a0b + ks * 32);
            unsigned a1 = lds32(a8b + ks * 32);
            unsigned a2 = lds32(a0b + ks * 32 + 16);
            unsigned a3 = lds32(a8b + ks * 32 + 16);
#pragma unroll
            for (int nt = 0; nt < 16; nt++) {
                unsigned baddr = bb + nt * 8 * 144 + ks * 32;
                unsigned b0 = lds32(baddr);
                unsigned b1 = lds32(baddr + 16);
                mma_bf16(acc[nt], a0, a1, a2, a3, b0, b1);
            }
        }
    }

    int w0 = mtile * 16 + lq;
    float* ob = g_i2s + ((((b << 6) | r) << 6) << 8);
#pragma unroll
    for (int nt = 0; nt < 16; nt++) {
        int o = nhalf * 128 + nt * 8 + 2 * l4;
        float b0v = bias[o], b1v = bias[o + 1];
        float2 v0 = make_float2(acc[nt][0] + b0v, acc[nt][1] + b1v);
        float2 v1 = make_float2(acc[nt][2] + b0v, acc[nt][3] + b1v);
        *(float2*)(ob + (w0 << 8) + o) = v0;
        *(float2*)(ob + ((w0 + 8) << 8) + o) = v1;
    }
}

// ---------------------------------------------------------------------------
// persistent scan (IDENTICAL to passing version)
// ---------------------------------------------------------------------------
#define OF_C    0
#define OF_HS   2048
#define OF_CS   4608
#define OF_P1   4736
#define OF_P2   12928
#define OF_WC   14976
#define SCAN_SMEM_BYTES (23168 * 4)

__global__ void __cluster_dims__(4, 1, 1) __launch_bounds__(512, 1)
scan_kernel(const float* __restrict__ w_s2s,
            const float* __restrict__ b_s2s,
            const float* __restrict__ w_c2c,
            const float* __restrict__ b_c2c,
            const float* __restrict__ b_i2s) {
    extern __shared__ float smp[];
    unsigned sbase = smem_u32(smp);

    int b = blockIdx.x >> 2, rg = blockIdx.x & 3;
    int r0 = rg << 4, q0 = rg << 2;
    int tid = threadIdx.x;
    int o = tid & 255, kh = tid >> 8;
    int j = tid & 63, g6 = tid >> 6;
    int quad = g6 & 3;
    int rq = g6;

    u64t wp0[16], wp1[16];
    {
        const float4* wp = (const float4*)(w_s2s + o * 128 + kh * 64);
#pragma unroll
        for (int k2 = 0; k2 < 16; k2++) {
            float4 v = wp[k2];
            wp0[k2] = pk(v.x, v.z);
            wp1[k2] = pk(v.y, v.w);
        }
    }
    float bcj = b_c2c[j];

    int rlA = 2 * rq, rlB = 2 * rq + 1;
    int aA = rlA >> 2;
    int ooA = ((rlA & 3) << 6) | j;
    int ooB = ((rlB & 3) << 6) | j;
    float bsA = b_s2s[ooA], bsB = b_s2s[ooB];
    float biA = b_i2s[ooA], biB = b_i2s[ooB];

    for (int i = tid; i < 8192; i += 512) {
        int kp = i >> 8, rr = i & 255, j2 = rr >> 2, s = (rr >> 1) & 1, e = rr & 1;
        smp[OF_WC + i] = w_c2c[(j2 * 64 + 2 * kp + e) * 2 + s];
    }
    for (int i = tid; i < 1024; i += 512) smp[OF_C + i] = 0.f;
    for (int i = tid; i < 2560; i += 512) smp[OF_HS + i] = 0.f;
    if (tid < 128) smp[OF_CS + tid] = 0.f;

    unsigned htg[2][2];
    unsigned ctg = 0;
#pragma unroll
    for (int i = 0; i < 2; i++) {
        int r = r0 + rq * 2 + i;
        htg[i][0] = 0; htg[i][1] = 0;
        int n = 0;
#pragma unroll
        for (int rg2 = 0; rg2 < 4; rg2++) {
            int v = r + 1 - 4 * rg2;
            if (v >= 0) {
                int mm = v >> 4, ii = v & 15;
                if (mm < 4 && ii < 5)
                    htg[i][n++] = mapa_rank(sbase + OF_HS * 4, rg2)
                                  + ((mm * 5 + ii) * 64 + j) * 4;
            }
        }
    }
    if (rq == 7 && rg < 3) ctg = mapa_rank(sbase + OF_CS * 4, rg + 1) + j * 4;

    unsigned wq = sbase + OF_WC * 4 + j * 16;

    for (int t = 0; t < NWD; t++) {
        int p = t & 1, np = 1 - p;

        float xg[8];
#pragma unroll
        for (int g = 0; g < 4; g++) {
            int qg = q0 + 16 * g + aA;
            int w = t - qg;
            bool in = (unsigned)w < 64u;
            const float* pa = g_i2s + ((((b << 6) | qg) << 6 | (w & 63)) << 8);
            xg[g]     = in ? pa[ooA] : biA;
            xg[4 + g] = in ? pa[ooB] : biB;
        }

        CLUSTER_SYNC();

        {
            unsigned hbB = sbase + (OF_HS + p * 1280) * 4 + kh * 128;
#pragma unroll
            for (int m = 0; m < 4; m++) {
                u64t a0 = 0, a1 = 0, a2 = 0, a3 = 0;
                unsigned hb = hbB + m * 1280;
#pragma unroll
                for (int k4 = 0; k4 < 8; k4++) {
                    u64t A0,A1,B0,B1,C0,C1,D0,D1,E0,E1;
                    lds2(A0, A1, hb + k4*16);
                    lds2(B0, B1, hb + 256 + k4*16);
                    lds2(C0, C1, hb + 512 + k4*16);
                    lds2(D0, D1, hb + 768 + k4*16);
                    lds2(E0, E1, hb + 1024 + k4*16);
                    int kp = 2 * k4;
                    fma2(a0, A0, wp0[kp]);   fma2(a0, B0, wp1[kp]);
                    fma2(a1, B0, wp0[kp]);   fma2(a1, C0, wp1[kp]);
                    fma2(a2, C0, wp0[kp]);   fma2(a2, D0, wp1[kp]);
                    fma2(a3, D0, wp0[kp]);   fma2(a3, E0, wp1[kp]);
                    fma2(a0, A1, wp0[kp+1]); fma2(a0, B1, wp1[kp+1]);
                    fma2(a1, B1, wp0[kp+1]); fma2(a1, C1, wp1[kp+1]);
                    fma2(a2, C1, wp0[kp+1]); fma2(a2, D1, wp1[kp+1]);
                    fma2(a3, D1, wp0[kp+1]); fma2(a3, E1, wp1[kp+1]);
                }
                float2 u;
                int base = OF_P1 + kh * 4096 + (m * 4) * 256 + o;
                u = upk(a0); smp[base]       = u.x + u.y;
                u = upk(a1); smp[base + 256] = u.x + u.y;
                u = upk(a2); smp[base + 512] = u.x + u.y;
                u = upk(a3); smp[base + 768] = u.x + u.y;
            }
        }

        {
            int rl0 = quad * 4;
            unsigned cb = sbase + (OF_C + (p << 10)) * 4;
            unsigned a_m1 = (rl0 == 0) ? (sbase + (OF_CS + p * 64) * 4 + kh * 128)
                                       : (cb + (rl0 - 1) * 256 + kh * 128);
            unsigned a_0 = cb + rl0 * 256 + kh * 128;
            int kpbase = kh * 16;
            u64t ac0 = 0, ac1 = 0, ac2 = 0, ac3 = 0;
#pragma unroll
            for (int k4 = 0; k4 < 8; k4++) {
                u64t w0A, w1A, w0B, w1B;
                lds2(w0A, w1A, wq + (kpbase + 2*k4) * 1024);
                lds2(w0B, w1B, wq + (kpbase + 2*k4 + 1) * 1024);
                u64t m0,m1, r00,r01, r10,r11, r20,r21, r30,r31;
                lds2(m0,  m1,  a_m1 + k4*16);
                lds2(r00, r01, a_0 + k4*16);
                lds2(r10, r11, a_0 + 256 + k4*16);
                lds2(r20, r21, a_0 + 512 + k4*16);
                lds2(r30, r31, a_0 + 768 + k4*16);
                fma2(ac0, m0,  w0A); fma2(ac0, r00, w1A);
                fma2(ac1, r00, w0A); fma2(ac1, r10, w1A);
                fma2(ac2, r10, w0A); fma2(ac2, r20, w1A);
                fma2(ac3, r20, w0A); fma2(ac3, r30, w1A);
                fma2(ac0, m1,  w0B); fma2(ac0, r01, w1B);
                fma2(ac1, r01, w0B); fma2(ac1, r11, w1B);
                fma2(ac2, r11, w0B); fma2(ac2, r21, w1B);
                fma2(ac3, r21, w0B); fma2(ac3, r31, w1B);
            }
            float2 u;
            int base = OF_P2 + kh * 1024 + rl0 * 64 + j;
            u = upk(ac0); smp[base]       = u.x + u.y;
            u = upk(ac1); smp[base + 64]  = u.x + u.y;
            u = upk(ac2); smp[base + 128] = u.x + u.y;
            u = upk(ac3); smp[base + 192] = u.x + u.y;
        }
        __syncthreads();

        {
            unsigned hpoff = np * 1280 * 4;
#pragma unroll
            for (int i = 0; i < 2; i++) {
                int rl = 2 * rq + i;
                int r = r0 + rl;
                int oo = i ? ooB : ooA;
                float bsv = i ? bsB : bsA;
                float acc = bcj + smp[OF_P2 + rl * 64 + j]
                                + smp[OF_P2 + 1024 + rl * 64 + j];
                float gate[4];
#pragma unroll
                for (int g = 0; g < 4; g++) {
                    int lr = g * 4 + aA;
                    float pv = smp[OF_P1 + lr * 256 + oo]
                             + smp[OF_P1 + 4096 + lr * 256 + oo];
                    gate[g] = sig_(xg[i * 4 + g] + bsv + pv);
                }
                float cv = gate[2] * acc + gate[0] * gate[1];
                float hv = gate[3] * tanh_(cv);
                smp[OF_C + (np << 10) + rl * 64 + j] = cv;
                if (htg[i][0]) stsc(htg[i][0] + hpoff, hv);
                if (htg[i][1]) stsc(htg[i][1] + hpoff, hv);
                if (i == 1 && ctg) stsc(ctg + np * 256, cv);
                int w = t - r;
                if ((unsigned)w < 64u)
                    g_hbuf[((((b << 6) | r) << 6 | w) << 6) | j] = hv;
            }
        }
    }

    CLUSTER_SYNC();
}

// ---------------------------------------------------------------------------
// up via mma.sync bf16 hi/lo: per block (b, r), M=64(w) x N=128(oc) x K=64(j).
// 8 warps = 4 mtiles x 2 nhalves (64 oc each). Epilogue: osm pitch-65 transpose
// then coalesced STG (validated in R10).
// ---------------------------------------------------------------------------
#define UXH_B  0            // [64][72 bf16]  9216
#define UXL_B  9216
#define UWH_B  18432        // [128][72 bf16] 18432
#define UWL_B  36864
#define UOS_B  55296        // osm [128][65] f32 = 33280
#define UBI_B  88576        // 128 floats
#define UP2_SMEM 89088

__global__ __launch_bounds__(256, 2) void up_mma(const float* __restrict__ b_up,
                                                 float* __restrict__ out) {
    extern __shared__ char usm[];
    unsigned sb = smem_u32(usm);
    unsigned* usw = (unsigned*)usm;
    float* osm = (float*)(usm + UOS_B);
    float* bias = (float*)(usm + UBI_B);
    int b = blockIdx.x >> 6, r = blockIdx.x & 63;
    int tid = threadIdx.x;

    // stage hbuf hi/lo: element (w, j) at row w*144 + j*2
    const float* src = g_hbuf + (((b << 6) | r) << 12);
    for (int i = tid; i < 4096; i += 256) {
        int w = i >> 6, j = i & 63;
        float x = src[i];
        __nv_bfloat16 h = __float2bfloat16(x);
        __nv_bfloat16 l = __float2bfloat16(x - __bfloat162float(h));
        *(__nv_bfloat16*)(usm + UXH_B + w * 144 + j * 2) = h;
        *(__nv_bfloat16*)(usm + UXL_B + w * 144 + j * 2) = l;
    }
    // stage w_up hi/lo: row oc (32 words) -> padded 36-word rows
    for (int i = tid; i < 4096; i += 256) {
        int o = i >> 5, cw = i & 31;
        usw[(UWH_B >> 2) + o * 36 + cw] = ((const unsigned*)g_ubf)[o * 32 + cw];
        usw[(UWL_B >> 2) + o * 36 + cw] = ((const unsigned*)g_ubf)[4096 + o * 32 + cw];
    }
    if (tid < 128) bias[tid] = b_up[tid];
    __syncthreads();

    int wid = tid >> 5, lane = tid & 31;
    int mtile = wid & 3, nhalf = wid >> 2;
    int lq = lane >> 2, l4 = lane & 3;

    float acc[8][4];
#pragma unroll
    for (int nt = 0; nt < 8; nt++) {
        acc[nt][0] = 0.f; acc[nt][1] = 0.f; acc[nt][2] = 0.f; acc[nt][3] = 0.f;
    }

    unsigned ax0h = sb + UXH_B + (mtile * 16 + lq) * 144 + l4 * 4;
    unsigned ax8h = ax0h + 8 * 144;
    unsigned ax0l = ax0h + (UXL_B - UXH_B);
    unsigned ax8l = ax8h + (UXL_B - UXH_B);
    unsigned bwh = sb + UWH_B + (nhalf * 64 + lq) * 144 + l4 * 4;
    unsigned bwl = bwh + (UWL_B - UWH_B);

#pragma unroll
    for (int pass = 0; pass < 3; pass++) {
        unsigned a0b = (pass < 2) ? ax0h : ax0l;
        unsigned a8b = (pass < 2) ? ax8h : ax8l;
        unsigned bb  = (pass == 1) ? bwl : bwh;
#pragma unroll
        for (int ks = 0; ks < 4; ks++) {
            unsigned a0 = lds32(a0b + ks * 32);
            unsigned a1 = lds32(a8b + ks * 32);
            unsigned a2 = lds32(a0b + ks * 32 + 16);
            unsigned a3 = lds32(a8b + ks * 32 + 16);
#pragma unroll
            for (int nt = 0; nt < 8; nt++) {
                unsigned baddr = bb + nt * 8 * 144 + ks * 32;
                unsigned b0 = lds32(baddr);
                unsigned b1 = lds32(baddr + 16);
                mma_bf16(acc[nt], a0, a1, a2, a3, b0, b1);
            }
        }
    }

    // epilogue: acc -> osm[oc][w] (pitch 65) with bias
    int w0 = mtile * 16 + lq;
#pragma unroll
    for (int nt = 0; nt < 8; nt++) {
        int o = nhalf * 64 + nt * 8 + 2 * l4;
        float b0v = bias[o], b1v = bias[o + 1];
        osm[o * 65 + w0]           = acc[nt][0] + b0v;
        osm[(o + 1) * 65 + w0]     = acc[nt][1] + b1v;
        osm[o * 65 + w0 + 8]       = acc[nt][2] + b0v;
        osm[(o + 1) * 65 + w0 + 8] = acc[nt][3] + b1v;
    }
    __syncthreads();

    // coalesced store: out[b][oc][r][w]
    float* ob = out + (size_t)b * 524288 + r * 64;
    for (int i = tid; i < 8192; i += 256) {
        int oc2 = i >> 6, w = i & 63;
        ob[oc2 * 4096 + w] = osm[oc2 * 65 + w];
    }
}

extern "C" void kernel_launch(void* const* d_in, const int* in_sizes, int n_in,
                              void* d_out, int out_size) {
    const float* inputs = (const float*)d_in[0];
    const float* w_i2s  = (const float*)d_in[1];
    const float* b_i2s  = (const float*)d_in[2];
    const float* w_s2s  = (const float*)d_in[3];
    const float* b_s2s  = (const float*)d_in[4];
    const float* w_c2c  = (const float*)d_in[5];
    const float* b_c2c  = (const float*)d_in[6];
    const float* w_up   = (const float*)d_in[7];
    const float* b_up   = (const float*)d_in[8];
    float* out = (float*)d_out;

    cudaFuncSetAttribute(i2s_mma, cudaFuncAttributeMaxDynamicSharedMemorySize, I2S_SMEM);
    cudaFuncSetAttribute(scan_kernel, cudaFuncAttributeMaxDynamicSharedMemorySize, SCAN_SMEM_BYTES);
    cudaFuncSetAttribute(up_mma, cudaFuncAttributeMaxDynamicSharedMemorySize, UP2_SMEM);

    prep_w<<<96, 256>>>(w_i2s, w_up);
    i2s_mma<<<2048, 256, I2S_SMEM>>>(inputs, b_i2s);
    scan_kernel<<<128, 512, SCAN_SMEM_BYTES>>>(w_s2s, b_s2s, w_c2c, b_c2c, b_i2s);
    up_mma<<<2048, 256, UP2_SMEM>>>(b_up, out);
}

// round 17
// speedup vs baseline: 3.1345x; 1.0952x over previous
#include <cuda_runtime.h>
#include <cuda_bf16.h>

#define BB 32
#define NWD 127

__device__ float g_i2s[BB * 64 * 64 * 256];   // [b][r][w][o] (includes b_i2s)
__device__ float g_hbuf[BB * 64 * 64 * 64];   // [b][r][w][j]
__device__ __nv_bfloat16 g_wbf[2 * 256 * 64]; // [hi/lo][o][c]   (w_i2s)
__device__ __nv_bfloat16 g_ubf[2 * 128 * 64]; // [hi/lo][oc][j]  (w_up)

typedef unsigned long long u64t;

__device__ __forceinline__ float sig_(float x) { return 1.0f / (1.0f + __expf(-x)); }
__device__ __forceinline__ float tanh_(float x) {
    float e = __expf(-2.0f * x);
    return __fdividef(1.0f - e, 1.0f + e);
}
__device__ __forceinline__ u64t pk(float lo, float hi) {
    u64t r; asm("mov.b64 %0, {%1,%2};" : "=l"(r) : "f"(lo), "f"(hi)); return r;
}
__device__ __forceinline__ float2 upk(u64t v) {
    float2 r; asm("mov.b64 {%0,%1}, %2;" : "=f"(r.x), "=f"(r.y) : "l"(v)); return r;
}
__device__ __forceinline__ void fma2(u64t& d, u64t a, u64t b) {
    asm("fma.rn.f32x2 %0, %1, %2, %0;" : "+l"(d) : "l"(a), "l"(b));
}
__device__ __forceinline__ void lds2(u64t& a, u64t& b, unsigned addr) {
    asm volatile("ld.shared.v2.u64 {%0,%1}, [%2];" : "=l"(a), "=l"(b) : "r"(addr));
}
__device__ __forceinline__ unsigned lds32(unsigned addr) {
    unsigned v;
    asm volatile("ld.shared.b32 %0, [%1];" : "=r"(v) : "r"(addr));
    return v;
}
__device__ __forceinline__ unsigned smem_u32(const void* p) {
    return (unsigned)__cvta_generic_to_shared(p);
}
__device__ __forceinline__ unsigned mapa_rank(unsigned addr, int rank) {
    unsigned r;
    asm("mapa.shared::cluster.u32 %0, %1, %2;" : "=r"(r) : "r"(addr), "r"(rank));
    return r;
}
__device__ __forceinline__ void stsc(unsigned addr, float v) {
    asm volatile("st.shared::cluster.f32 [%0], %1;" :: "r"(addr), "f"(v) : "memory");
}
#define CLUSTER_SYNC() do { \
    asm volatile("barrier.cluster.arrive.aligned;" ::: "memory"); \
    asm volatile("barrier.cluster.wait.aligned;" ::: "memory"); \
} while (0)

__device__ __forceinline__ void mma_bf16(float* d, unsigned a0, unsigned a1,
                                         unsigned a2, unsigned a3,
                                         unsigned b0, unsigned b1) {
    asm volatile(
        "mma.sync.aligned.m16n8k16.row.col.f32.bf16.bf16.f32 "
        "{%0,%1,%2,%3}, {%4,%5,%6,%7}, {%8,%9}, {%0,%1,%2,%3};"
        : "+f"(d[0]), "+f"(d[1]), "+f"(d[2]), "+f"(d[3])
        : "r"(a0), "r"(a1), "r"(a2), "r"(a3), "r"(b0), "r"(b1));
}

// ---------------------------------------------------------------------------
// prep: split w_i2s (16384) and w_up (8192) into bf16 hi/lo
// ---------------------------------------------------------------------------
__global__ void prep_w(const float* __restrict__ w_i2s,
                       const float* __restrict__ w_up) {
    int i = blockIdx.x * 256 + threadIdx.x;  // 24576
    if (i < 16384) {
        float x = w_i2s[i];
        __nv_bfloat16 hi = __float2bfloat16(x);
        g_wbf[i] = hi;
        g_wbf[16384 + i] = __float2bfloat16(x - __bfloat162float(hi));
    } else {
        int k = i - 16384;
        float x = w_up[k];
        __nv_bfloat16 hi = __float2bfloat16(x);
        g_ubf[k] = hi;
        g_ubf[8192 + k] = __float2bfloat16(x - __bfloat162float(hi));
    }
}

// ---------------------------------------------------------------------------
// i2s via mma.sync bf16 hi/lo (unchanged from passing R15/R16)
// ---------------------------------------------------------------------------
#define XH_B   0
#define XL_B   9216
#define WH_B   18432
#define WL_B   55296
#define BIAS_B 92160
#define I2S_SMEM 93184

__global__ __launch_bounds__(256, 2) void i2s_mma(const float* __restrict__ inputs,
                                                  const float* __restrict__ b_i2s) {
    extern __shared__ char ism[];
    unsigned sb = smem_u32(ism);
    unsigned* ismw = (unsigned*)ism;
    float* bias = (float*)(ism + BIAS_B);
    int b = blockIdx.x >> 6, r = blockIdx.x & 63;
    int tid = threadIdx.x;

    for (int i = tid; i < 4096; i += 256) {
        int c = i >> 6, w = i & 63;
        float x = inputs[((((b << 6) | c) << 6 | r) << 6) | w];
        __nv_bfloat16 h = __float2bfloat16(x);
        __nv_bfloat16 l = __float2bfloat16(x - __bfloat162float(h));
        *(__nv_bfloat16*)(ism + XH_B + w * 144 + c * 2) = h;
        *(__nv_bfloat16*)(ism + XL_B + w * 144 + c * 2) = l;
    }
    for (int i = tid; i < 8192; i += 256) {
        int o = i >> 5, cw = i & 31;
        ismw[(WH_B >> 2) + o * 36 + cw] = ((const unsigned*)g_wbf)[o * 32 + cw];
        ismw[(WL_B >> 2) + o * 36 + cw] = ((const unsigned*)g_wbf)[8192 + o * 32 + cw];
    }
    bias[tid] = b_i2s[tid];
    __syncthreads();

    int wid = tid >> 5, lane = tid & 31;
    int mtile = wid & 3, nhalf = wid >> 2;
    int lq = lane >> 2, l4 = lane & 3;

    float acc[16][4];
#pragma unroll
    for (int nt = 0; nt < 16; nt++) {
        acc[nt][0] = 0.f; acc[nt][1] = 0.f; acc[nt][2] = 0.f; acc[nt][3] = 0.f;
    }

    unsigned ax0h = sb + XH_B + (mtile * 16 + lq) * 144 + l4 * 4;
    unsigned ax8h = ax0h + 8 * 144;
    unsigned ax0l = ax0h + (XL_B - XH_B);
    unsigned ax8l = ax8h + (XL_B - XH_B);
    unsigned bwh = sb + WH_B + (nhalf * 128 + lq) * 144 + l4 * 4;
    unsigned bwl = bwh + (WL_B - WH_B);

#pragma unroll
    for (int pass = 0; pass < 3; pass++) {
        unsigned a0b = (pass < 2) ? ax0h : ax0l;
        unsigned a8b = (pass < 2) ? ax8h : ax8l;
        unsigned bb  = (pass == 1) ? bwl : bwh;
#pragma unroll
        for (int ks = 0; ks < 4; ks++) {
            unsigned a0 = lds32(a0b + ks * 32);
            unsigned a1 = lds32(a8b + ks * 32);
            unsigned a2 = lds32(a0b + ks * 32 + 16);
            unsigned a3 = lds32(a8b + ks * 32 + 16);
#pragma unroll
            for (int nt = 0; nt < 16; nt++) {
                unsigned baddr = bb + nt * 8 * 144 + ks * 32;
                unsigned b0 = lds32(baddr);
                unsigned b1 = lds32(baddr + 16);
                mma_bf16(acc[nt], a0, a1, a2, a3, b0, b1);
            }
        }
    }

    int w0 = mtile * 16 + lq;
    float* ob = g_i2s + ((((b << 6) | r) << 6) << 8);
#pragma unroll
    for (int nt = 0; nt < 16; nt++) {
        int o = nhalf * 128 + nt * 8 + 2 * l4;
        float b0v = bias[o], b1v = bias[o + 1];
        float2 v0 = make_float2(acc[nt][0] + b0v, acc[nt][1] + b1v);
        float2 v1 = make_float2(acc[nt][2] + b0v, acc[nt][3] + b1v);
        *(float2*)(ob + (w0 << 8) + o) = v0;
        *(float2*)(ob + ((w0 + 8) << 8) + o) = v1;
    }
}

// ---------------------------------------------------------------------------
// persistent scan: phase-1 via HMMA (A=[16][128] h-state hi/lo re-split each
// step; B=[256][128] w_s2s hi/lo staged once), phase-2 fp32 split-K unchanged.
// smem byte offsets:
#define SB_C    0        // c_st       2x1024 f32   8192
#define SB_HS   8192     // hstage     2x1280 f32  10240
#define SB_CS   18432    // cstage     2x64   f32    512
#define SB_P1   18944    // P1         16x256 f32  16384
#define SB_P2   35328    // P2         2x1024 f32   8192
#define SB_AH   43520    // A hi       16x272 B     4352
#define SB_AL   47872    // A lo                    4352
#define SB_BH   52224    // B hi       256x272 B   69632
#define SB_BL   121856   // B lo                   69632
#define SB_WC   191488   // wc         8192 f32    32768
#define SCAN_SMEM_BYTES  224256
// float-index bases:
#define FI_HS 2048
#define FI_CS 4608
#define FI_P1 4736
#define FI_P2 8832
#define FI_WC 47872
// ---------------------------------------------------------------------------
__global__ void __cluster_dims__(4, 1, 1) __launch_bounds__(512, 1)
scan_kernel(const float* __restrict__ w_s2s,
            const float* __restrict__ b_s2s,
            const float* __restrict__ w_c2c,
            const float* __restrict__ b_c2c,
            const float* __restrict__ b_i2s) {
    extern __shared__ float smp[];
    char* smb = (char*)smp;
    unsigned sbase = smem_u32(smp);

    int b = blockIdx.x >> 2, rg = blockIdx.x & 3;
    int r0 = rg << 4, q0 = rg << 2;
    int tid = threadIdx.x;
    int wid = tid >> 5, lane = tid & 31;
    int lq = lane >> 2, l4 = lane & 3;
    int j = tid & 63, g6 = tid >> 6;
    int quad = g6 & 3, kh = tid >> 8;
    int rq = g6;

    float bcj = b_c2c[j];

    // consumer-side constants: cells (2rq+i, j)
    int rlA = 2 * rq, rlB = 2 * rq + 1;
    int aA = rlA >> 2;
    int ooA = ((rlA & 3) << 6) | j;
    int ooB = ((rlB & 3) << 6) | j;
    float bsA = b_s2s[ooA], bsB = b_s2s[ooB];
    float biA = b_i2s[ooA], biB = b_i2s[ooB];

    // stage B = [Ws0 | Ws1] hi/lo once (padded 272-B rows)
    for (int e = tid; e < 32768; e += 512) {
        int o2 = e >> 7, k = e & 127;
        float v = w_s2s[o2 * 128 + (k & 63) * 2 + (k >> 6)];
        __nv_bfloat16 h = __float2bfloat16(v);
        __nv_bfloat16 l = __float2bfloat16(v - __bfloat162float(h));
        *(__nv_bfloat16*)(smb + SB_BH + o2 * 272 + k * 2) = h;
        *(__nv_bfloat16*)(smb + SB_BL + o2 * 272 + k * 2) = l;
    }
    // wc fill (phase-2 weights, packed pairs)
    for (int i = tid; i < 8192; i += 512) {
        int kp = i >> 8, rr = i & 255, j2 = rr >> 2, s = (rr >> 1) & 1, e = rr & 1;
        smp[FI_WC + i] = w_c2c[(j2 * 64 + 2 * kp + e) * 2 + s];
    }
    for (int i = tid; i < 1024; i += 512) smp[i] = 0.f;          // c_st
    for (int i = tid; i < 2560; i += 512) smp[FI_HS + i] = 0.f;  // hstage
    if (tid < 128) smp[FI_CS + tid] = 0.f;                       // cstage

    // push targets for rows r = r0 + 2*rq + i
    unsigned htg[2][2];
    unsigned ctg = 0;
#pragma unroll
    for (int i = 0; i < 2; i++) {
        int r = r0 + rq * 2 + i;
        htg[i][0] = 0; htg[i][1] = 0;
        int n = 0;
#pragma unroll
        for (int rg2 = 0; rg2 < 4; rg2++) {
            int v = r + 1 - 4 * rg2;
            if (v >= 0) {
                int mm = v >> 4, ii = v & 15;
                if (mm < 4 && ii < 5)
                    htg[i][n++] = mapa_rank(sbase + SB_HS, rg2)
                                  + ((mm * 5 + ii) * 64 + j) * 4;
            }
        }
    }
    if (rq == 7 && rg < 3) ctg = mapa_rank(sbase + SB_CS, rg + 1) + j * 4;

    unsigned wq = sbase + SB_WC + j * 16;  // + kp*1024

    for (int t = 0; t < NWD; t++) {
        int p = t & 1, np = 1 - p;

        // prefetch xi at consumer coordinates
        float xg[8];
#pragma unroll
        for (int g = 0; g < 4; g++) {
            int qg = q0 + 16 * g + aA;
            int w = t - qg;
            bool in = (unsigned)w < 64u;
            const float* pa = g_i2s + ((((b << 6) | qg) << 6 | (w & 63)) << 8);
            xg[g]     = in ? pa[ooA] : biA;
            xg[4 + g] = in ? pa[ooB] : biB;
        }

        CLUSTER_SYNC();  // pushes from step t-1 visible; hstage[p]/c_st[p] ready

        // ---- stage A hi/lo from hstage[p] (A[lr][k]: k<64 -> h[p_lr-1]) ----
        {
            const float* hsrc = smp + FI_HS + p * 1280;
#pragma unroll
            for (int q = 0; q < 4; q++) {
                int e = tid + q * 512;
                int lr = e >> 7, k = e & 127;
                int m = lr >> 2, i = lr & 3;
                float v = hsrc[m * 320 + (i + (k >> 6)) * 64 + (k & 63)];
                __nv_bfloat16 h = __float2bfloat16(v);
                __nv_bfloat16 l = __float2bfloat16(v - __bfloat162float(h));
                *(__nv_bfloat16*)(smb + SB_AH + lr * 272 + k * 2) = h;
                *(__nv_bfloat16*)(smb + SB_AL + lr * 272 + k * 2) = l;
            }
        }
        __syncthreads();  // A staged

        // ---- phase 1: HMMA, warp wid covers o = wid*16 .. wid*16+15 ----
        {
            float acc[2][4];
            acc[0][0] = 0.f; acc[0][1] = 0.f; acc[0][2] = 0.f; acc[0][3] = 0.f;
            acc[1][0] = 0.f; acc[1][1] = 0.f; acc[1][2] = 0.f; acc[1][3] = 0.f;
            unsigned aH = sbase + SB_AH + lq * 272 + l4 * 4;
            unsigned aL = aH + (SB_AL - SB_AH);
#pragma unroll
            for (int pass = 0; pass < 3; pass++) {
                unsigned ab = (pass < 2) ? aH : aL;
                unsigned bbase = sbase + ((pass == 1) ? SB_BL : SB_BH)
                               + (wid * 16 + lq) * 272 + l4 * 4;
#pragma unroll
                for (int ks = 0; ks < 8; ks++) {
                    unsigned a0 = lds32(ab + ks * 32);
                    unsigned a1 = lds32(ab + 2176 + ks * 32);
                    unsigned a2 = lds32(ab + ks * 32 + 16);
                    unsigned a3 = lds32(ab + 2176 + ks * 32 + 16);
                    unsigned b0 = lds32(bbase + ks * 32);
                    unsigned b1 = lds32(bbase + ks * 32 + 16);
                    mma_bf16(acc[0], a0, a1, a2, a3, b0, b1);
                    unsigned b2 = lds32(bbase + 8 * 272 + ks * 32);
                    unsigned b3 = lds32(bbase + 8 * 272 + ks * 32 + 16);
                    mma_bf16(acc[1], a0, a1, a2, a3, b2, b3);
                }
            }
#pragma unroll
            for (int nt = 0; nt < 2; nt++) {
                int oo2 = wid * 16 + nt * 8 + 2 * l4;
                smp[FI_P1 + lq * 256 + oo2]           = acc[nt][0];
                smp[FI_P1 + lq * 256 + oo2 + 1]       = acc[nt][1];
                smp[FI_P1 + (lq + 8) * 256 + oo2]     = acc[nt][2];
                smp[FI_P1 + (lq + 8) * 256 + oo2 + 1] = acc[nt][3];
            }
        }

        // ---- phase 2 partials: fp32 split-K (unchanged) ----
        {
            int rl0 = quad * 4;
            unsigned cb = sbase + SB_C + (p << 12);
            unsigned a_m1 = (rl0 == 0) ? (sbase + SB_CS + p * 256 + kh * 128)
                                       : (cb + (rl0 - 1) * 256 + kh * 128);
            unsigned a_0 = cb + rl0 * 256 + kh * 128;
            int kpbase = kh * 16;
            u64t ac0 = 0, ac1 = 0, ac2 = 0, ac3 = 0;
#pragma unroll
            for (int k4 = 0; k4 < 8; k4++) {
                u64t w0A, w1A, w0B, w1B;
                lds2(w0A, w1A, wq + (kpbase + 2*k4) * 1024);
                lds2(w0B, w1B, wq + (kpbase + 2*k4 + 1) * 1024);
                u64t m0,m1, r00,r01, r10,r11, r20,r21, r30,r31;
                lds2(m0,  m1,  a_m1 + k4*16);
                lds2(r00, r01, a_0 + k4*16);
                lds2(r10, r11, a_0 + 256 + k4*16);
                lds2(r20, r21, a_0 + 512 + k4*16);
                lds2(r30, r31, a_0 + 768 + k4*16);
                fma2(ac0, m0,  w0A); fma2(ac0, r00, w1A);
                fma2(ac1, r00, w0A); fma2(ac1, r10, w1A);
                fma2(ac2, r10, w0A); fma2(ac2, r20, w1A);
                fma2(ac3, r20, w0A); fma2(ac3, r30, w1A);
                fma2(ac0, m1,  w0B); fma2(ac0, r01, w1B);
                fma2(ac1, r01, w0B); fma2(ac1, r11, w1B);
                fma2(ac2, r11, w0B); fma2(ac2, r21, w1B);
                fma2(ac3, r21, w0B); fma2(ac3, r31, w1B);
            }
            float2 u;
            int base = FI_P2 + kh * 1024 + rl0 * 64 + j;
            u = upk(ac0); smp[base]       = u.x + u.y;
            u = upk(ac1); smp[base + 64]  = u.x + u.y;
            u = upk(ac2); smp[base + 128] = u.x + u.y;
            u = upk(ac3); smp[base + 192] = u.x + u.y;
        }
        __syncthreads();  // P1, P2 visible

        // ---- fused combine: gates + cell/hidden update + pushes ----
        {
            unsigned hpoff = np * 1280 * 4;
#pragma unroll
            for (int i = 0; i < 2; i++) {
                int rl = 2 * rq + i;
                int r = r0 + rl;
                int oo = i ? ooB : ooA;
                float bsv = i ? bsB : bsA;
                float acc = bcj + smp[FI_P2 + rl * 64 + j]
                                + smp[FI_P2 + 1024 + rl * 64 + j];
                float gate[4];
#pragma unroll
                for (int g = 0; g < 4; g++) {
                    int lr = g * 4 + aA;
                    float pv = smp[FI_P1 + lr * 256 + oo];
                    gate[g] = sig_(xg[i * 4 + g] + bsv + pv);
                }
                float cv = gate[2] * acc + gate[0] * gate[1];
                float hv = gate[3] * tanh_(cv);
                smp[(np << 10) + rl * 64 + j] = cv;
                if (htg[i][0]) stsc(htg[i][0] + hpoff, hv);
                if (htg[i][1]) stsc(htg[i][1] + hpoff, hv);
                if (i == 1 && ctg) stsc(ctg + np * 256, cv);
                int w = t - r;
                if ((unsigned)w < 64u)
                    g_hbuf[((((b << 6) | r) << 6 | w) << 6) | j] = hv;
            }
        }
    }

    CLUSTER_SYNC();  // exit-race guard for in-flight cluster stores
}

// ---------------------------------------------------------------------------
// up via mma.sync bf16 hi/lo (unchanged from passing R16)
// ---------------------------------------------------------------------------
#define UXH_B  0
#define UXL_B  9216
#define UWH_B  18432
#define UWL_B  36864
#define UOS_B  55296
#define UBI_B  88576
#define UP2_SMEM 89088

__global__ __launch_bounds__(256, 2) void up_mma(const float* __restrict__ b_up,
                                                 float* __restrict__ out) {
    extern __shared__ char usm[];
    unsigned sb = smem_u32(usm);
    unsigned* usw = (unsigned*)usm;
    float* osm = (float*)(usm + UOS_B);
    float* bias = (float*)(usm + UBI_B);
    int b = blockIdx.x >> 6, r = blockIdx.x & 63;
    int tid = threadIdx.x;

    const float* src = g_hbuf + (((b << 6) | r) << 12);
    for (int i = tid; i < 4096; i += 256) {
        int w = i >> 6, j = i & 63;
        float x = src[i];
        __nv_bfloat16 h = __float2bfloat16(x);
        __nv_bfloat16 l = __float2bfloat16(x - __bfloat162float(h));
        *(__nv_bfloat16*)(usm + UXH_B + w * 144 + j * 2) = h;
        *(__nv_bfloat16*)(usm + UXL_B + w * 144 + j * 2) = l;
    }
    for (int i = tid; i < 4096; i += 256) {
        int o = i >> 5, cw = i & 31;
        usw[(UWH_B >> 2) + o * 36 + cw] = ((const unsigned*)g_ubf)[o * 32 + cw];
        usw[(UWL_B >> 2) + o * 36 + cw] = ((const unsigned*)g_ubf)[4096 + o * 32 + cw];
    }
    if (tid < 128) bias[tid] = b_up[tid];
    __syncthreads();

    int wid = tid >> 5, lane = tid & 31;
    int mtile = wid & 3, nhalf = wid >> 2;
    int lq = lane >> 2, l4 = lane & 3;

    float acc[8][4];
#pragma unroll
    for (int nt = 0; nt < 8; nt++) {
        acc[nt][0] = 0.f; acc[nt][1] = 0.f; acc[nt][2] = 0.f; acc[nt][3] = 0.f;
    }

    unsigned ax0h = sb + UXH_B + (mtile * 16 + lq) * 144 + l4 * 4;
    unsigned ax8h = ax0h + 8 * 144;
    unsigned ax0l = ax0h + (UXL_B - UXH_B);
    unsigned ax8l = ax8h + (UXL_B - UXH_B);
    unsigned bwh = sb + UWH_B + (nhalf * 64 + lq) * 144 + l4 * 4;
    unsigned bwl = bwh + (UWL_B - UWH_B);

#pragma unroll
    for (int pass = 0; pass < 3; pass++) {
        unsigned a0b = (pass < 2) ? ax0h : ax0l;
        unsigned a8b = (pass < 2) ? ax8h : ax8l;
        unsigned bb  = (pass == 1) ? bwl : bwh;
#pragma unroll
        for (int ks = 0; ks < 4; ks++) {
            unsigned a0 = lds32(a0b + ks * 32);
            unsigned a1 = lds32(a8b + ks * 32);
            unsigned a2 = lds32(a0b + ks * 32 + 16);
            unsigned a3 = lds32(a8b + ks * 32 + 16);
#pragma unroll
            for (int nt = 0; nt < 8; nt++) {
                unsigned baddr = bb + nt * 8 * 144 + ks * 32;
                unsigned b0 = lds32(baddr);
                unsigned b1 = lds32(baddr + 16);
                mma_bf16(acc[nt], a0, a1, a2, a3, b0, b1);
            }
        }
    }

    int w0 = mtile * 16 + lq;
#pragma unroll
    for (int nt = 0; nt < 8; nt++) {
        int o = nhalf * 64 + nt * 8 + 2 * l4;
        float b0v = bias[o], b1v = bias[o + 1];
        osm[o * 65 + w0]           = acc[nt][0] + b0v;
        osm[(o + 1) * 65 + w0]     = acc[nt][1] + b1v;
        osm[o * 65 + w0 + 8]       = acc[nt][2] + b0v;
        osm[(o + 1) * 65 + w0 + 8] = acc[nt][3] + b1v;
    }
    __syncthreads();

    float* ob = out + (size_t)b * 524288 + r * 64;
    for (int i = tid; i < 8192; i += 256) {
        int oc2 = i >> 6, w = i & 63;
        ob[oc2 * 4096 + w] = osm[oc2 * 65 + w];
    }
}

extern "C" void kernel_launch(void* const* d_in, const int* in_sizes, int n_in,
                              void* d_out, int out_size) {
    const float* inputs = (const float*)d_in[0];
    const float* w_i2s  = (const float*)d_in[1];
    const float* b_i2s  = (const float*)d_in[2];
    const float* w_s2s  = (const float*)d_in[3];
    const float* b_s2s  = (const float*)d_in[4];
    const float* w_c2c  = (const float*)d_in[5];
    const float* b_c2c  = (const float*)d_in[6];
    const float* w_up   = (const float*)d_in[7];
    const float* b_up   = (const float*)d_in[8];
    float* out = (float*)d_out;

    cudaFuncSetAttribute(i2s_mma, cudaFuncAttributeMaxDynamicSharedMemorySize, I2S_SMEM);
    cudaFuncSetAttribute(scan_kernel, cudaFuncAttributeMaxDynamicSharedMemorySize, SCAN_SMEM_BYTES);
    cudaFuncSetAttribute(up_mma, cudaFuncAttributeMaxDynamicSharedMemorySize, UP2_SMEM);

    prep_w<<<96, 256>>>(w_i2s, w_up);
    i2s_mma<<<2048, 256, I2S_SMEM>>>(inputs, b_i2s);
    scan_kernel<<<128, 512, SCAN_SMEM_BYTES>>>(w_s2s, b_s2s, w_c2c, b_c2c, b_i2s);
    up_mma<<<2048, 256, UP2_SMEM>>>(b_up, out);
}